// round 8
// baseline (speedup 1.0000x reference)
#include <cuda_runtime.h>
#include <cstdint>

#define BB 16
#define NN 1024
#define CC 768
#define HH 9
#define HD 64
#define M_TOK (BB * NN)        // 16384
#define QKV_N (3 * HH * HD)    // 1728
#define ATT_N (HH * HD)        // 576

// Scratch (device globals — no allocation allowed)
__device__ float g_q[BB * HH * NN * HD];     // [B,H,N,HD]
__device__ float g_k[BB * HH * NN * HD];
__device__ float g_v[BB * HH * NN * HD];
__device__ float g_att[M_TOK * ATT_N];       // [B,N,H*HD]

// ---------------------------------------------------------------------------
// TF32 helpers
// ---------------------------------------------------------------------------
__device__ __forceinline__ uint32_t f2tf(float x) {
    uint32_t r;
    asm("cvt.rna.tf32.f32 %0, %1;" : "=r"(r) : "f"(x));
    return r;
}

// D(16x8,f32) += A(16x8,tf32,row) * B(8x8,tf32,col)
__device__ __forceinline__ void mma_tf32(float* d,
    uint32_t a0, uint32_t a1, uint32_t a2, uint32_t a3,
    uint32_t b0, uint32_t b1)
{
    asm volatile(
        "mma.sync.aligned.m16n8k8.row.col.f32.tf32.tf32.f32 "
        "{%0,%1,%2,%3}, {%4,%5,%6,%7}, {%8,%9}, {%0,%1,%2,%3};"
        : "+f"(d[0]), "+f"(d[1]), "+f"(d[2]), "+f"(d[3])
        : "r"(a0), "r"(a1), "r"(a2), "r"(a3), "r"(b0), "r"(b1));
}

// ---------------------------------------------------------------------------
// GEMM (tensor core): C[M,N] = A[M,K] @ B[N,K]^T + bias.
// Block 128x192, BK=32, 192 threads = 6 warps in 2(M)x3(N), warp tile 64x64.
// Per k-step: 16 A regs + 16 B regs -> 32 MMAs => 16 FLOP / smem byte
// (2x the old 32x32 warp tile). smem stride 36 -> conflict-free frag loads.
// MODE 0: A = x, scatter into g_q/g_k/g_v (each warp's 64 cols = one head chunk).
// MODE 1: A = g_att, plain store.
// ---------------------------------------------------------------------------
template <int MODE>
__global__ __launch_bounds__(192) void gemm_tc(
    const float* __restrict__ A, const float* __restrict__ Bw,
    const float* __restrict__ bias, float* __restrict__ C,
    int M, int N, int K)
{
    __shared__ uint32_t As[128][36];
    __shared__ uint32_t Bs[192][36];

    const int tid  = threadIdx.x;
    const int lane = tid & 31;
    const int warp = tid >> 5;          // 0..5
    const int wm = warp / 3;            // 0..1  (M groups of 64)
    const int wn = warp % 3;            // 0..2  (N groups of 64)
    const int g = lane >> 2, t = lane & 3;
    const int bm = blockIdx.x * 128;
    const int bn = blockIdx.y * 192;

    const float* Ab = (MODE == 0) ? A : g_att;

    float acc[4][8][4];
#pragma unroll
    for (int mt = 0; mt < 4; mt++)
#pragma unroll
        for (int nt = 0; nt < 8; nt++)
#pragma unroll
            for (int i = 0; i < 4; i++) acc[mt][nt][i] = 0.0f;

    for (int k0 = 0; k0 < K; k0 += 32) {
        // A tile: 128x32 = 1024 float4
        for (int idx = tid; idx < 1024; idx += 192) {
            int r = idx >> 3, c = (idx & 7) << 2;
            float4 v = *(const float4*)(Ab + (size_t)(bm + r) * K + k0 + c);
            As[r][c]     = f2tf(v.x);
            As[r][c + 1] = f2tf(v.y);
            As[r][c + 2] = f2tf(v.z);
            As[r][c + 3] = f2tf(v.w);
        }
        // B tile: 192x32 = 1536 float4 (exactly 8 per thread)
#pragma unroll
        for (int i = 0; i < 8; i++) {
            int idx = tid + 192 * i;
            int r = idx >> 3, c = (idx & 7) << 2;
            float4 v = *(const float4*)(Bw + (size_t)(bn + r) * K + k0 + c);
            Bs[r][c]     = f2tf(v.x);
            Bs[r][c + 1] = f2tf(v.y);
            Bs[r][c + 2] = f2tf(v.z);
            Bs[r][c + 3] = f2tf(v.w);
        }
        __syncthreads();

#pragma unroll
        for (int ks = 0; ks < 4; ks++) {
            const int kk = ks * 8;
            uint32_t a[4][4], b[8][2];
#pragma unroll
            for (int mt = 0; mt < 4; mt++) {
                int r = wm * 64 + mt * 16 + g;
                a[mt][0] = As[r][kk + t];
                a[mt][1] = As[r + 8][kk + t];
                a[mt][2] = As[r][kk + t + 4];
                a[mt][3] = As[r + 8][kk + t + 4];
            }
#pragma unroll
            for (int nt = 0; nt < 8; nt++) {
                int n = wn * 64 + nt * 8 + g;
                b[nt][0] = Bs[n][kk + t];
                b[nt][1] = Bs[n][kk + t + 4];
            }
#pragma unroll
            for (int mt = 0; mt < 4; mt++)
#pragma unroll
                for (int nt = 0; nt < 8; nt++)
                    mma_tf32(acc[mt][nt], a[mt][0], a[mt][1], a[mt][2], a[mt][3],
                             b[nt][0], b[nt][1]);
        }
        __syncthreads();
    }

    // Epilogue. Each warp's 64 cols are 64-aligned -> exactly one q/k/v head chunk.
    const int coff = bn + wn * 64;
    if (MODE == 0) {
        const int which = coff / 576;
        const int h     = (coff % 576) >> 6;
        float* dst = (which == 0) ? g_q : (which == 1) ? g_k : g_v;
#pragma unroll
        for (int mt = 0; mt < 4; mt++) {
#pragma unroll
            for (int half = 0; half < 2; half++) {
                int m = bm + wm * 64 + mt * 16 + g + half * 8;
                int b_ = m >> 10, tok = m & 1023;
                float* rowp = dst + (((size_t)(b_ * HH + h) << 10) + tok) * HD;
#pragma unroll
                for (int nt = 0; nt < 8; nt++) {
                    int d = nt * 8 + t * 2;
                    int col = coff + d;
                    float2 r = make_float2(acc[mt][nt][half * 2]     + bias[col],
                                           acc[mt][nt][half * 2 + 1] + bias[col + 1]);
                    *(float2*)(rowp + d) = r;
                }
            }
        }
    } else {
#pragma unroll
        for (int mt = 0; mt < 4; mt++) {
#pragma unroll
            for (int half = 0; half < 2; half++) {
                int m = bm + wm * 64 + mt * 16 + g + half * 8;
#pragma unroll
                for (int nt = 0; nt < 8; nt++) {
                    int col = coff + nt * 8 + t * 2;
                    float2 r = make_float2(acc[mt][nt][half * 2]     + bias[col],
                                           acc[mt][nt][half * 2 + 1] + bias[col + 1]);
                    *(float2*)&C[(size_t)m * N + col] = r;
                }
            }
        }
    }
}

// ---------------------------------------------------------------------------
// Flash attention (tensor core): block = 128 queries of one (b,h), KV tiles 64.
// 4 warps (128 threads); each warp owns 32 query rows end-to-end (mt=2 of 16),
// raising FLOP/smem-byte from 6.4 to 10.7. Softmax stays warp-private.
// S = Q@K^T via mma (Q pre-scaled), fp32 online softmax in registers,
// P -> smem (tf32) -> PV mma. V stored transposed [d][key] with XOR swizzle.
// Dynamic smem: Qs 128x68 + Ks 64x68 + Vs 64x64 + Ps 128x68 = 103424 B.
// ---------------------------------------------------------------------------
#define ATTN_SMEM_BYTES (128*68*4 + 64*68*4 + 64*64*4 + 128*68*4)

__device__ __forceinline__ int vsw(int d, int key) {  // Vs swizzled flat index
    return d * 64 + (key ^ ((d & 7) << 2));
}

__global__ __launch_bounds__(128) void attn_tc()
{
    extern __shared__ char sraw[];
    uint32_t (*Qs)[68] = reinterpret_cast<uint32_t(*)[68]>(sraw);
    uint32_t (*Ks)[68] = reinterpret_cast<uint32_t(*)[68]>(sraw + 128 * 68 * 4);
    uint32_t* VsF      = reinterpret_cast<uint32_t*>(sraw + (128 + 64) * 68 * 4);
    uint32_t (*Ps)[68] = reinterpret_cast<uint32_t(*)[68]>(sraw + (128 + 64) * 68 * 4 + 64 * 64 * 4);

    const int tid  = threadIdx.x;
    const int lane = tid & 31;
    const int warp = tid >> 5;                 // 0..3
    const int g = lane >> 2, t = lane & 3;
    const int bh = blockIdx.y;                 // 0..143
    const int q0 = blockIdx.x * 128;
    const int qr = warp * 32;                  // warp's 32 query rows

    const float* Qg = g_q + ((size_t)bh * NN + q0) * HD;
    const float* Kg = g_k + (size_t)bh * NN * HD;
    const float* Vg = g_v + (size_t)bh * NN * HD;

    // Load Q tile (pre-scaled by 1/sqrt(64)): 128x64 = 2048 float4
#pragma unroll
    for (int i = 0; i < 16; i++) {
        int idx = tid + 128 * i;
        int r = idx >> 4, c = (idx & 15) << 2;
        float4 v = ((const float4*)Qg)[idx];
        Qs[r][c]     = f2tf(v.x * 0.125f);
        Qs[r][c + 1] = f2tf(v.y * 0.125f);
        Qs[r][c + 2] = f2tf(v.z * 0.125f);
        Qs[r][c + 3] = f2tf(v.w * 0.125f);
    }

    float m_i[2][2], l_i[2][2], o[2][8][4];
#pragma unroll
    for (int mt = 0; mt < 2; mt++) {
        m_i[mt][0] = -1e30f; m_i[mt][1] = -1e30f;
        l_i[mt][0] = 0.0f;   l_i[mt][1] = 0.0f;
#pragma unroll
        for (int nt = 0; nt < 8; nt++)
#pragma unroll
            for (int i = 0; i < 4; i++) o[mt][nt][i] = 0.0f;
    }

    for (int kt = 0; kt < NN; kt += 64) {
        __syncthreads();   // prev iter's MMAs done with Ks/Vs

        // K tile 64x64 (row-coalesced)
#pragma unroll
        for (int i = 0; i < 8; i++) {
            int idx = tid + 128 * i;
            int r = idx >> 4, c = (idx & 15) << 2;
            float4 kv = *(const float4*)(Kg + (size_t)(kt + r) * HD + c);
            Ks[r][c]     = f2tf(kv.x);
            Ks[r][c + 1] = f2tf(kv.y);
            Ks[r][c + 2] = f2tf(kv.z);
            Ks[r][c + 3] = f2tf(kv.w);
        }
        // V tile transposed into Vs[d][key]
#pragma unroll
        for (int i = 0; i < 8; i++) {
            int idx = tid + 128 * i;
            int r = idx & 63;            // key
            int c = (idx >> 6) << 2;     // d base
            float4 vv = *(const float4*)(Vg + (size_t)(kt + r) * HD + c);
            VsF[vsw(c,     r)] = f2tf(vv.x);
            VsF[vsw(c + 1, r)] = f2tf(vv.y);
            VsF[vsw(c + 2, r)] = f2tf(vv.z);
            VsF[vsw(c + 3, r)] = f2tf(vv.w);
        }
        __syncthreads();

        // S[32x64] = Q(warp rows) @ K^T
        float s[2][8][4];
#pragma unroll
        for (int mt = 0; mt < 2; mt++)
#pragma unroll
            for (int nt = 0; nt < 8; nt++)
#pragma unroll
                for (int i = 0; i < 4; i++) s[mt][nt][i] = 0.0f;

#pragma unroll
        for (int ks = 0; ks < 8; ks++) {
            const int kk = ks * 8;
            uint32_t a[2][4], b[8][2];
#pragma unroll
            for (int mt = 0; mt < 2; mt++) {
                int r = qr + mt * 16 + g;
                a[mt][0] = Qs[r][kk + t];
                a[mt][1] = Qs[r + 8][kk + t];
                a[mt][2] = Qs[r][kk + t + 4];
                a[mt][3] = Qs[r + 8][kk + t + 4];
            }
#pragma unroll
            for (int nt = 0; nt < 8; nt++) {
                int n = nt * 8 + g;
                b[nt][0] = Ks[n][kk + t];
                b[nt][1] = Ks[n][kk + t + 4];
            }
#pragma unroll
            for (int mt = 0; mt < 2; mt++)
#pragma unroll
                for (int nt = 0; nt < 8; nt++)
                    mma_tf32(s[mt][nt], a[mt][0], a[mt][1], a[mt][2], a[mt][3],
                             b[nt][0], b[nt][1]);
        }

        // Online softmax per mt: rows r0 = qr+mt*16+g (elems 0,1), r1 = r0+8 (2,3)
#pragma unroll
        for (int mt = 0; mt < 2; mt++) {
            float mt0 = -1e30f, mt1 = -1e30f;
#pragma unroll
            for (int nt = 0; nt < 8; nt++) {
                mt0 = fmaxf(mt0, fmaxf(s[mt][nt][0], s[mt][nt][1]));
                mt1 = fmaxf(mt1, fmaxf(s[mt][nt][2], s[mt][nt][3]));
            }
            mt0 = fmaxf(mt0, __shfl_xor_sync(0xffffffffu, mt0, 1));
            mt0 = fmaxf(mt0, __shfl_xor_sync(0xffffffffu, mt0, 2));
            mt1 = fmaxf(mt1, __shfl_xor_sync(0xffffffffu, mt1, 1));
            mt1 = fmaxf(mt1, __shfl_xor_sync(0xffffffffu, mt1, 2));

            float mn0 = fmaxf(m_i[mt][0], mt0), mn1 = fmaxf(m_i[mt][1], mt1);
            float c0 = __expf(m_i[mt][0] - mn0), c1 = __expf(m_i[mt][1] - mn1);
            m_i[mt][0] = mn0; m_i[mt][1] = mn1;

            float rs0 = 0.0f, rs1 = 0.0f;
            const int r0 = qr + mt * 16 + g;
#pragma unroll
            for (int nt = 0; nt < 8; nt++) {
                float p00 = __expf(s[mt][nt][0] - mn0);
                float p01 = __expf(s[mt][nt][1] - mn0);
                float p10 = __expf(s[mt][nt][2] - mn1);
                float p11 = __expf(s[mt][nt][3] - mn1);
                rs0 += p00 + p01;
                rs1 += p10 + p11;
                int col = nt * 8 + t * 2;
                *(uint2*)&Ps[r0][col]     = make_uint2(f2tf(p00), f2tf(p01));
                *(uint2*)&Ps[r0 + 8][col] = make_uint2(f2tf(p10), f2tf(p11));
            }
            rs0 += __shfl_xor_sync(0xffffffffu, rs0, 1);
            rs0 += __shfl_xor_sync(0xffffffffu, rs0, 2);
            rs1 += __shfl_xor_sync(0xffffffffu, rs1, 1);
            rs1 += __shfl_xor_sync(0xffffffffu, rs1, 2);
            l_i[mt][0] = l_i[mt][0] * c0 + rs0;
            l_i[mt][1] = l_i[mt][1] * c1 + rs1;
#pragma unroll
            for (int nt = 0; nt < 8; nt++) {
                o[mt][nt][0] *= c0; o[mt][nt][1] *= c0;
                o[mt][nt][2] *= c1; o[mt][nt][3] *= c1;
            }
        }
        __syncwarp();   // Ps rows are warp-private

        // O[32x64] += P[32x64] @ V[64x64]
#pragma unroll
        for (int ks = 0; ks < 8; ks++) {
            const int kk = ks * 8;
            uint32_t a[2][4], b[8][2];
#pragma unroll
            for (int mt = 0; mt < 2; mt++) {
                int r = qr + mt * 16 + g;
                a[mt][0] = Ps[r][kk + t];
                a[mt][1] = Ps[r + 8][kk + t];
                a[mt][2] = Ps[r][kk + t + 4];
                a[mt][3] = Ps[r + 8][kk + t + 4];
            }
#pragma unroll
            for (int nt = 0; nt < 8; nt++) {
                int n = nt * 8 + g;
                b[nt][0] = VsF[vsw(n, kk + t)];
                b[nt][1] = VsF[vsw(n, kk + t + 4)];
            }
#pragma unroll
            for (int mt = 0; mt < 2; mt++)
#pragma unroll
                for (int nt = 0; nt < 8; nt++)
                    mma_tf32(o[mt][nt], a[mt][0], a[mt][1], a[mt][2], a[mt][3],
                             b[nt][0], b[nt][1]);
        }
    }

    // Epilogue: normalize, write g_att [B,N,H*HD]
    const int b_ = bh / HH;
    const int h  = bh - b_ * HH;
#pragma unroll
    for (int mt = 0; mt < 2; mt++) {
        const float inv0 = 1.0f / l_i[mt][0];
        const float inv1 = 1.0f / l_i[mt][1];
        const int tok0 = q0 + qr + mt * 16 + g;
        const int tok1 = tok0 + 8;
        float* p0 = g_att + (size_t)(b_ * NN + tok0) * ATT_N + h * HD;
        float* p1 = g_att + (size_t)(b_ * NN + tok1) * ATT_N + h * HD;
#pragma unroll
        for (int nt = 0; nt < 8; nt++) {
            int d = nt * 8 + t * 2;
            *(float2*)(p0 + d) = make_float2(o[mt][nt][0] * inv0, o[mt][nt][1] * inv0);
            *(float2*)(p1 + d) = make_float2(o[mt][nt][2] * inv1, o[mt][nt][3] * inv1);
        }
    }
}

// ---------------------------------------------------------------------------
extern "C" void kernel_launch(void* const* d_in, const int* in_sizes, int n_in,
                              void* d_out, int out_size)
{
    const float* x      = (const float*)d_in[0];
    const float* qkv_w  = (const float*)d_in[1];
    const float* qkv_b  = (const float*)d_in[2];
    const float* proj_w = (const float*)d_in[3];
    const float* proj_b = (const float*)d_in[4];
    float* out = (float*)d_out;

    cudaFuncSetAttribute(attn_tc, cudaFuncAttributeMaxDynamicSharedMemorySize,
                         ATTN_SMEM_BYTES);

    // 1) QKV projection + bias + scatter to [B,H,N,HD]
    dim3 g1(M_TOK / 128, QKV_N / 192);
    gemm_tc<0><<<g1, 192>>>(x, qkv_w, qkv_b, nullptr, M_TOK, QKV_N, CC);

    // 2) Flash attention -> g_att [B,N,H*HD]
    dim3 g2(NN / 128, BB * HH);
    attn_tc<<<g2, 128, ATTN_SMEM_BYTES>>>();

    // 3) Output projection + bias
    dim3 g3(M_TOK / 128, CC / 192);
    gemm_tc<1><<<g3, 192>>>(nullptr, proj_w, proj_b, out, M_TOK, CC, ATT_N);
}

// round 9
// speedup vs baseline: 1.1473x; 1.1473x over previous
#include <cuda_runtime.h>
#include <cstdint>

#define BB 16
#define NN 1024
#define CC 768
#define HH 9
#define HD 64
#define M_TOK (BB * NN)        // 16384
#define QKV_N (3 * HH * HD)    // 1728
#define ATT_N (HH * HD)        // 576

// Scratch (device globals — no allocation allowed)
__device__ float g_q[BB * HH * NN * HD];     // [B,H,N,HD]
__device__ float g_k[BB * HH * NN * HD];
__device__ float g_v[BB * HH * NN * HD];
__device__ float g_att[M_TOK * ATT_N];       // [B,N,H*HD]

// ---------------------------------------------------------------------------
// TF32 / async-copy helpers
// ---------------------------------------------------------------------------
__device__ __forceinline__ uint32_t f2tf(float x) {
    uint32_t r;
    asm("cvt.rna.tf32.f32 %0, %1;" : "=r"(r) : "f"(x));
    return r;
}

__device__ __forceinline__ void cp16(void* smem_dst, const void* gmem_src) {
    uint32_t sa = (uint32_t)__cvta_generic_to_shared(smem_dst);
    asm volatile("cp.async.cg.shared.global [%0], [%1], 16;"
                 :: "r"(sa), "l"(gmem_src));
}
__device__ __forceinline__ void cp_commit() {
    asm volatile("cp.async.commit_group;");
}
template <int N>
__device__ __forceinline__ void cp_wait() {
    asm volatile("cp.async.wait_group %0;" :: "n"(N));
}

// D(16x8,f32) += A(16x8,tf32,row) * B(8x8,tf32,col)
__device__ __forceinline__ void mma_tf32(float* d,
    uint32_t a0, uint32_t a1, uint32_t a2, uint32_t a3,
    uint32_t b0, uint32_t b1)
{
    asm volatile(
        "mma.sync.aligned.m16n8k8.row.col.f32.tf32.tf32.f32 "
        "{%0,%1,%2,%3}, {%4,%5,%6,%7}, {%8,%9}, {%0,%1,%2,%3};"
        : "+f"(d[0]), "+f"(d[1]), "+f"(d[2]), "+f"(d[3])
        : "r"(a0), "r"(a1), "r"(a2), "r"(a3), "r"(b0), "r"(b1));
}

// ---------------------------------------------------------------------------
// GEMM (tensor core): C[M,N] = A[M,K] @ B[N,K]^T + bias.
// Block 128x192, BK=32, 192 threads = 6 warps in 2(M)x3(N), warp tile 64x64.
// 2-stage cp.async double buffering: smem holds raw f32 (2 x (128+192) x 36),
// tf32 conversion at fragment-load time. smem stride 36 -> frag bank = 4g+t
// = lane/8-group, conflict-free.
// MODE 0: A = x, scatter into g_q/g_k/g_v. MODE 1: A = g_att, plain store.
// ---------------------------------------------------------------------------
#define GEMM_SMEM_BYTES ((2 * 128 * 36 + 2 * 192 * 36) * 4)

template <int MODE>
__global__ __launch_bounds__(192) void gemm_tc(
    const float* __restrict__ A, const float* __restrict__ Bw,
    const float* __restrict__ bias, float* __restrict__ C,
    int M, int N, int K)
{
    extern __shared__ float dsm[];
    float* AsBuf[2] = { dsm, dsm + 128 * 36 };
    float* BsBuf[2] = { dsm + 2 * 128 * 36, dsm + 2 * 128 * 36 + 192 * 36 };

    const int tid  = threadIdx.x;
    const int lane = tid & 31;
    const int warp = tid >> 5;          // 0..5
    const int wm = warp / 3;            // 0..1  (M groups of 64)
    const int wn = warp % 3;            // 0..2  (N groups of 64)
    const int g = lane >> 2, t = lane & 3;
    const int bm = blockIdx.x * 128;
    const int bn = blockIdx.y * 192;

    const float* Ab = (MODE == 0) ? A : g_att;

    float acc[4][8][4];
#pragma unroll
    for (int mt = 0; mt < 4; mt++)
#pragma unroll
        for (int nt = 0; nt < 8; nt++)
#pragma unroll
            for (int i = 0; i < 4; i++) acc[mt][nt][i] = 0.0f;

    // Async tile fetch: A 128x32 (1024 16B chunks), B 192x32 (1536 chunks)
    auto issue = [&](int stage, int k0) {
        float* Asd = AsBuf[stage];
        float* Bsd = BsBuf[stage];
        for (int idx = tid; idx < 1024; idx += 192) {
            int r = idx >> 3, c = (idx & 7) << 2;
            cp16(&Asd[r * 36 + c], Ab + (size_t)(bm + r) * K + k0 + c);
        }
#pragma unroll
        for (int i = 0; i < 8; i++) {
            int idx = tid + 192 * i;
            int r = idx >> 3, c = (idx & 7) << 2;
            cp16(&Bsd[r * 36 + c], Bw + (size_t)(bn + r) * K + k0 + c);
        }
        cp_commit();
    };

    const int nIter = K / 32;
    issue(0, 0);

    for (int it = 0; it < nIter; it++) {
        const int stage = it & 1;
        if (it + 1 < nIter) {
            issue(stage ^ 1, (it + 1) * 32);
            cp_wait<1>();
        } else {
            cp_wait<0>();
        }
        __syncthreads();

        const float* Asd = AsBuf[stage];
        const float* Bsd = BsBuf[stage];
#pragma unroll
        for (int ks = 0; ks < 4; ks++) {
            const int kk = ks * 8;
            uint32_t a[4][4], b[8][2];
#pragma unroll
            for (int mt = 0; mt < 4; mt++) {
                int r = wm * 64 + mt * 16 + g;
                a[mt][0] = f2tf(Asd[r * 36 + kk + t]);
                a[mt][1] = f2tf(Asd[(r + 8) * 36 + kk + t]);
                a[mt][2] = f2tf(Asd[r * 36 + kk + t + 4]);
                a[mt][3] = f2tf(Asd[(r + 8) * 36 + kk + t + 4]);
            }
#pragma unroll
            for (int nt = 0; nt < 8; nt++) {
                int n = wn * 64 + nt * 8 + g;
                b[nt][0] = f2tf(Bsd[n * 36 + kk + t]);
                b[nt][1] = f2tf(Bsd[n * 36 + kk + t + 4]);
            }
#pragma unroll
            for (int mt = 0; mt < 4; mt++)
#pragma unroll
                for (int nt = 0; nt < 8; nt++)
                    mma_tf32(acc[mt][nt], a[mt][0], a[mt][1], a[mt][2], a[mt][3],
                             b[nt][0], b[nt][1]);
        }
        __syncthreads();   // all reads of this stage done before it is refilled
    }

    // Epilogue. Each warp's 64 cols are 64-aligned -> exactly one q/k/v head chunk.
    const int coff = bn + wn * 64;
    if (MODE == 0) {
        const int which = coff / 576;
        const int h     = (coff % 576) >> 6;
        float* dst = (which == 0) ? g_q : (which == 1) ? g_k : g_v;
#pragma unroll
        for (int mt = 0; mt < 4; mt++) {
#pragma unroll
            for (int half = 0; half < 2; half++) {
                int m = bm + wm * 64 + mt * 16 + g + half * 8;
                int b_ = m >> 10, tok = m & 1023;
                float* rowp = dst + (((size_t)(b_ * HH + h) << 10) + tok) * HD;
#pragma unroll
                for (int nt = 0; nt < 8; nt++) {
                    int d = nt * 8 + t * 2;
                    int col = coff + d;
                    float2 r = make_float2(acc[mt][nt][half * 2]     + bias[col],
                                           acc[mt][nt][half * 2 + 1] + bias[col + 1]);
                    *(float2*)(rowp + d) = r;
                }
            }
        }
    } else {
#pragma unroll
        for (int mt = 0; mt < 4; mt++) {
#pragma unroll
            for (int half = 0; half < 2; half++) {
                int m = bm + wm * 64 + mt * 16 + g + half * 8;
#pragma unroll
                for (int nt = 0; nt < 8; nt++) {
                    int col = coff + nt * 8 + t * 2;
                    float2 r = make_float2(acc[mt][nt][half * 2]     + bias[col],
                                           acc[mt][nt][half * 2 + 1] + bias[col + 1]);
                    *(float2*)&C[(size_t)m * N + col] = r;
                }
            }
        }
    }
}

// ---------------------------------------------------------------------------
// Flash attention (tensor core): block = 128 queries of one (b,h), KV tiles 32.
// 4 warps (128 threads); each warp owns 32 query rows end-to-end.
// 2-stage cp.async double buffering of K and V (raw f32, row-major):
//   K [32][68] (bank 4g+t, conflict-free B-frags)
//   V [32][72] (72 mod 32 = 8 -> bank 8t+g, conflict-free PV B-frags, no transpose)
// Q stays tf32 [128][68]; P stored tf32 [128][36].
// smem = (128*68 + 2*32*68 + 2*32*72 + 128*36)*4 = 89088 B -> 2 blocks/SM.
// ---------------------------------------------------------------------------
#define ATTN_SMEM_BYTES ((128*68 + 2*32*68 + 2*32*72 + 128*36) * 4)

__global__ __launch_bounds__(128) void attn_tc()
{
    extern __shared__ char sraw[];
    uint32_t (*Qs)[68] = reinterpret_cast<uint32_t(*)[68]>(sraw);
    float* KsB = reinterpret_cast<float*>(sraw + 128 * 68 * 4);
    float* VsB = reinterpret_cast<float*>(sraw + (128 * 68 + 2 * 32 * 68) * 4);
    uint32_t (*Ps)[36] = reinterpret_cast<uint32_t(*)[36]>(
        sraw + (128 * 68 + 2 * 32 * 68 + 2 * 32 * 72) * 4);

    const int tid  = threadIdx.x;
    const int lane = tid & 31;
    const int warp = tid >> 5;                 // 0..3
    const int g = lane >> 2, t = lane & 3;
    const int bh = blockIdx.y;                 // 0..143
    const int q0 = blockIdx.x * 128;
    const int qr = warp * 32;                  // warp's 32 query rows

    const float* Qg = g_q + ((size_t)bh * NN + q0) * HD;
    const float* Kg = g_k + (size_t)bh * NN * HD;
    const float* Vg = g_v + (size_t)bh * NN * HD;

    // Async KV tile fetch: K 32x64 (512 chunks), V 32x64 (512 chunks)
    auto issue = [&](int stage, int kt) {
        float* Kd = KsB + stage * 32 * 68;
        float* Vd = VsB + stage * 32 * 72;
#pragma unroll
        for (int i = 0; i < 4; i++) {
            int idx = tid + 128 * i;
            int r = idx >> 4, c = (idx & 15) << 2;
            cp16(&Kd[r * 68 + c], Kg + (size_t)(kt + r) * HD + c);
        }
#pragma unroll
        for (int i = 0; i < 4; i++) {
            int idx = tid + 128 * i;
            int r = idx >> 4, c = (idx & 15) << 2;
            cp16(&Vd[r * 72 + c], Vg + (size_t)(kt + r) * HD + c);
        }
        cp_commit();
    };

    issue(0, 0);

    // Load Q tile (pre-scaled by 1/sqrt(64)): 128x64 = 2048 float4
#pragma unroll
    for (int i = 0; i < 16; i++) {
        int idx = tid + 128 * i;
        int r = idx >> 4, c = (idx & 15) << 2;
        float4 v = ((const float4*)Qg)[idx];
        Qs[r][c]     = f2tf(v.x * 0.125f);
        Qs[r][c + 1] = f2tf(v.y * 0.125f);
        Qs[r][c + 2] = f2tf(v.z * 0.125f);
        Qs[r][c + 3] = f2tf(v.w * 0.125f);
    }

    float m_i[2][2], l_i[2][2], o[2][8][4];
#pragma unroll
    for (int mt = 0; mt < 2; mt++) {
        m_i[mt][0] = -1e30f; m_i[mt][1] = -1e30f;
        l_i[mt][0] = 0.0f;   l_i[mt][1] = 0.0f;
#pragma unroll
        for (int nt = 0; nt < 8; nt++)
#pragma unroll
            for (int i = 0; i < 4; i++) o[mt][nt][i] = 0.0f;
    }

    const int nIter = NN / 32;   // 32
    for (int it = 0; it < nIter; it++) {
        const int stage = it & 1;
        if (it + 1 < nIter) {
            issue(stage ^ 1, (it + 1) * 32);
            cp_wait<1>();
        } else {
            cp_wait<0>();
        }
        __syncthreads();

        const float* Kd = KsB + stage * 32 * 68;
        const float* Vd = VsB + stage * 32 * 72;

        // S[32x32] = Q(warp rows) @ K^T   (keys = 32 -> nt 0..3)
        float s[2][4][4];
#pragma unroll
        for (int mt = 0; mt < 2; mt++)
#pragma unroll
            for (int nt = 0; nt < 4; nt++)
#pragma unroll
                for (int i = 0; i < 4; i++) s[mt][nt][i] = 0.0f;

#pragma unroll
        for (int ks = 0; ks < 8; ks++) {
            const int kk = ks * 8;
            uint32_t a[2][4], b[4][2];
#pragma unroll
            for (int mt = 0; mt < 2; mt++) {
                int r = qr + mt * 16 + g;
                a[mt][0] = Qs[r][kk + t];
                a[mt][1] = Qs[r + 8][kk + t];
                a[mt][2] = Qs[r][kk + t + 4];
                a[mt][3] = Qs[r + 8][kk + t + 4];
            }
#pragma unroll
            for (int nt = 0; nt < 4; nt++) {
                int n = nt * 8 + g;
                b[nt][0] = f2tf(Kd[n * 68 + kk + t]);
                b[nt][1] = f2tf(Kd[n * 68 + kk + t + 4]);
            }
#pragma unroll
            for (int mt = 0; mt < 2; mt++)
#pragma unroll
                for (int nt = 0; nt < 4; nt++)
                    mma_tf32(s[mt][nt], a[mt][0], a[mt][1], a[mt][2], a[mt][3],
                             b[nt][0], b[nt][1]);
        }

        // Online softmax per mt: rows r0 = qr+mt*16+g (elems 0,1), r1 = r0+8 (2,3)
#pragma unroll
        for (int mt = 0; mt < 2; mt++) {
            float mt0 = -1e30f, mt1 = -1e30f;
#pragma unroll
            for (int nt = 0; nt < 4; nt++) {
                mt0 = fmaxf(mt0, fmaxf(s[mt][nt][0], s[mt][nt][1]));
                mt1 = fmaxf(mt1, fmaxf(s[mt][nt][2], s[mt][nt][3]));
            }
            mt0 = fmaxf(mt0, __shfl_xor_sync(0xffffffffu, mt0, 1));
            mt0 = fmaxf(mt0, __shfl_xor_sync(0xffffffffu, mt0, 2));
            mt1 = fmaxf(mt1, __shfl_xor_sync(0xffffffffu, mt1, 1));
            mt1 = fmaxf(mt1, __shfl_xor_sync(0xffffffffu, mt1, 2));

            float mn0 = fmaxf(m_i[mt][0], mt0), mn1 = fmaxf(m_i[mt][1], mt1);
            float c0 = __expf(m_i[mt][0] - mn0), c1 = __expf(m_i[mt][1] - mn1);
            m_i[mt][0] = mn0; m_i[mt][1] = mn1;

            float rs0 = 0.0f, rs1 = 0.0f;
            const int r0 = qr + mt * 16 + g;
#pragma unroll
            for (int nt = 0; nt < 4; nt++) {
                float p00 = __expf(s[mt][nt][0] - mn0);
                float p01 = __expf(s[mt][nt][1] - mn0);
                float p10 = __expf(s[mt][nt][2] - mn1);
                float p11 = __expf(s[mt][nt][3] - mn1);
                rs0 += p00 + p01;
                rs1 += p10 + p11;
                int col = nt * 8 + t * 2;
                *(uint2*)&Ps[r0][col]     = make_uint2(f2tf(p00), f2tf(p01));
                *(uint2*)&Ps[r0 + 8][col] = make_uint2(f2tf(p10), f2tf(p11));
            }
            rs0 += __shfl_xor_sync(0xffffffffu, rs0, 1);
            rs0 += __shfl_xor_sync(0xffffffffu, rs0, 2);
            rs1 += __shfl_xor_sync(0xffffffffu, rs1, 1);
            rs1 += __shfl_xor_sync(0xffffffffu, rs1, 2);
            l_i[mt][0] = l_i[mt][0] * c0 + rs0;
            l_i[mt][1] = l_i[mt][1] * c1 + rs1;
#pragma unroll
            for (int nt = 0; nt < 8; nt++) {
                o[mt][nt][0] *= c0; o[mt][nt][1] *= c0;
                o[mt][nt][2] *= c1; o[mt][nt][3] *= c1;
            }
        }
        __syncwarp();   // Ps rows are warp-private

        // O[32x64] += P[32x32] @ V[32x64]
#pragma unroll
        for (int ks = 0; ks < 4; ks++) {
            const int kk = ks * 8;
            uint32_t a[2][4], b[8][2];
#pragma unroll
            for (int mt = 0; mt < 2; mt++) {
                int r = qr + mt * 16 + g;
                a[mt][0] = Ps[r][kk + t];
                a[mt][1] = Ps[r + 8][kk + t];
                a[mt][2] = Ps[r][kk + t + 4];
                a[mt][3] = Ps[r + 8][kk + t + 4];
            }
#pragma unroll
            for (int nt = 0; nt < 8; nt++) {
                int n = nt * 8 + g;
                b[nt][0] = f2tf(Vd[(kk + t) * 72 + n]);
                b[nt][1] = f2tf(Vd[(kk + t + 4) * 72 + n]);
            }
#pragma unroll
            for (int mt = 0; mt < 2; mt++)
#pragma unroll
                for (int nt = 0; nt < 8; nt++)
                    mma_tf32(o[mt][nt], a[mt][0], a[mt][1], a[mt][2], a[mt][3],
                             b[nt][0], b[nt][1]);
        }
        __syncthreads();   // all reads of this K/V stage done before refill
    }

    // Epilogue: normalize, write g_att [B,N,H*HD]
    const int b_ = bh / HH;
    const int h  = bh - b_ * HH;
#pragma unroll
    for (int mt = 0; mt < 2; mt++) {
        const float inv0 = 1.0f / l_i[mt][0];
        const float inv1 = 1.0f / l_i[mt][1];
        const int tok0 = q0 + qr + mt * 16 + g;
        const int tok1 = tok0 + 8;
        float* p0 = g_att + (size_t)(b_ * NN + tok0) * ATT_N + h * HD;
        float* p1 = g_att + (size_t)(b_ * NN + tok1) * ATT_N + h * HD;
#pragma unroll
        for (int nt = 0; nt < 8; nt++) {
            int d = nt * 8 + t * 2;
            *(float2*)(p0 + d) = make_float2(o[mt][nt][0] * inv0, o[mt][nt][1] * inv0);
            *(float2*)(p1 + d) = make_float2(o[mt][nt][2] * inv1, o[mt][nt][3] * inv1);
        }
    }
}

// ---------------------------------------------------------------------------
extern "C" void kernel_launch(void* const* d_in, const int* in_sizes, int n_in,
                              void* d_out, int out_size)
{
    const float* x      = (const float*)d_in[0];
    const float* qkv_w  = (const float*)d_in[1];
    const float* qkv_b  = (const float*)d_in[2];
    const float* proj_w = (const float*)d_in[3];
    const float* proj_b = (const float*)d_in[4];
    float* out = (float*)d_out;

    cudaFuncSetAttribute(gemm_tc<0>, cudaFuncAttributeMaxDynamicSharedMemorySize,
                         GEMM_SMEM_BYTES);
    cudaFuncSetAttribute(gemm_tc<1>, cudaFuncAttributeMaxDynamicSharedMemorySize,
                         GEMM_SMEM_BYTES);
    cudaFuncSetAttribute(attn_tc, cudaFuncAttributeMaxDynamicSharedMemorySize,
                         ATTN_SMEM_BYTES);

    // 1) QKV projection + bias + scatter to [B,H,N,HD]
    dim3 g1(M_TOK / 128, QKV_N / 192);
    gemm_tc<0><<<g1, 192, GEMM_SMEM_BYTES>>>(x, qkv_w, qkv_b, nullptr,
                                             M_TOK, QKV_N, CC);

    // 2) Flash attention -> g_att [B,N,H*HD]
    dim3 g2(NN / 128, BB * HH);
    attn_tc<<<g2, 128, ATTN_SMEM_BYTES>>>();

    // 3) Output projection + bias
    dim3 g3(M_TOK / 128, CC / 192);
    gemm_tc<1><<<g3, 192, GEMM_SMEM_BYTES>>>(nullptr, proj_w, proj_b, out,
                                             M_TOK, CC, ATT_N);
}

// round 10
// speedup vs baseline: 1.4980x; 1.3058x over previous
#include <cuda_runtime.h>
#include <cstdint>

#define BB 16
#define NN 1024
#define CC 768
#define HH 9
#define HD 64
#define M_TOK (BB * NN)        // 16384
#define QKV_N (3 * HH * HD)    // 1728
#define ATT_N (HH * HD)        // 576

// Scratch (device globals — no allocation allowed)
__device__ float g_q[BB * HH * NN * HD];     // [B,H,N,HD]  (tf32-rounded, Q pre-scaled)
__device__ float g_k[BB * HH * NN * HD];
__device__ float g_v[BB * HH * NN * HD];
__device__ float g_att[M_TOK * ATT_N];       // [B,N,H*HD]  (tf32-rounded)
__device__ float g_xt[M_TOK * CC];           // tf32-rounded copies of inputs
__device__ float g_wqkv[QKV_N * CC];
__device__ float g_wproj[CC * ATT_N];

// ---------------------------------------------------------------------------
// TF32 / async-copy helpers
// ---------------------------------------------------------------------------
__device__ __forceinline__ uint32_t f2tf(float x) {
    uint32_t r;
    asm("cvt.rna.tf32.f32 %0, %1;" : "=r"(r) : "f"(x));
    return r;
}
__device__ __forceinline__ uint32_t U(float x) { return __float_as_uint(x); }

__device__ __forceinline__ void cp16(void* smem_dst, const void* gmem_src) {
    uint32_t sa = (uint32_t)__cvta_generic_to_shared(smem_dst);
    asm volatile("cp.async.cg.shared.global [%0], [%1], 16;"
                 :: "r"(sa), "l"(gmem_src));
}
__device__ __forceinline__ void cp_commit() {
    asm volatile("cp.async.commit_group;");
}
template <int N>
__device__ __forceinline__ void cp_wait() {
    asm volatile("cp.async.wait_group %0;" :: "n"(N));
}

// D(16x8,f32) += A(16x8,tf32,row) * B(8x8,tf32,col)
__device__ __forceinline__ void mma_tf32(float* d,
    uint32_t a0, uint32_t a1, uint32_t a2, uint32_t a3,
    uint32_t b0, uint32_t b1)
{
    asm volatile(
        "mma.sync.aligned.m16n8k8.row.col.f32.tf32.tf32.f32 "
        "{%0,%1,%2,%3}, {%4,%5,%6,%7}, {%8,%9}, {%0,%1,%2,%3};"
        : "+f"(d[0]), "+f"(d[1]), "+f"(d[2]), "+f"(d[3])
        : "r"(a0), "r"(a1), "r"(a2), "r"(a3), "r"(b0), "r"(b1));
}

// ---------------------------------------------------------------------------
// Pre-round inputs to tf32 in global memory (removes all CVT from MMA loops).
// DST: 0 -> g_xt, 1 -> g_wqkv, 2 -> g_wproj. n4 = element count / 4.
// ---------------------------------------------------------------------------
template <int DST>
__global__ __launch_bounds__(256) void cvt_tf32(const float* __restrict__ src, int n4)
{
    float* dst = (DST == 0) ? g_xt : (DST == 1) ? g_wqkv : g_wproj;
    int i = blockIdx.x * 256 + threadIdx.x;
    if (i < n4) {
        float4 v = ((const float4*)src)[i];
        uint4 r = make_uint4(f2tf(v.x), f2tf(v.y), f2tf(v.z), f2tf(v.w));
        ((uint4*)dst)[i] = r;
    }
}

// ---------------------------------------------------------------------------
// GEMM (tensor core): C[M,N] = A[M,K] @ B[N,K]^T + bias. Operands pre-tf32.
// Block 128x192, BK=32, 256 threads = 8 warps in 2(M)x4(N), warp tile 64x48.
// 3-stage cp.async ring, ONE __syncthreads per k-iter (issue into stage
// (it+2)%3 is safe right after the barrier: all warps finished reading that
// stage in iter it-1). Empty commit_group at the tail keeps wait<1> counting.
// smem stride 36 -> frag bank = 4g+t = lane id pattern, conflict-free.
// MODE 0: A=g_xt, B=g_wqkv, scatter tf32-rounded into g_q (x0.125)/g_k/g_v.
// MODE 1: A=g_att, B=g_wproj, plain f32 store + bias.
// ---------------------------------------------------------------------------
#define GEMM_SMEM_BYTES (3 * (128 + 192) * 36 * 4)   // 138240

template <int MODE>
__global__ __launch_bounds__(256) void gemm_tc(
    const float* __restrict__ bias, float* __restrict__ C,
    int M, int N, int K)
{
    extern __shared__ float dsm[];

    const int tid  = threadIdx.x;
    const int lane = tid & 31;
    const int warp = tid >> 5;          // 0..7
    const int wm = warp >> 2;           // 0..1  (M groups of 64)
    const int wn = warp & 3;            // 0..3  (N groups of 48)
    const int g = lane >> 2, t = lane & 3;
    const int bm = blockIdx.x * 128;
    const int bn = blockIdx.y * 192;

    const float* Ab = (MODE == 0) ? g_xt  : g_att;
    const float* Bb = (MODE == 0) ? g_wqkv : g_wproj;

    float acc[4][6][4];
#pragma unroll
    for (int mt = 0; mt < 4; mt++)
#pragma unroll
        for (int nt = 0; nt < 6; nt++)
#pragma unroll
            for (int i = 0; i < 4; i++) acc[mt][nt][i] = 0.0f;

    // Stage s: A tile at dsm + s*320*36 (128x36), B tile right after (192x36)
    auto issue = [&](int stage, int k0) {
        float* Asd = dsm + stage * (320 * 36);
        float* Bsd = Asd + 128 * 36;
#pragma unroll
        for (int i = 0; i < 4; i++) {               // A: 1024 16B chunks
            int idx = tid + 256 * i;
            int r = idx >> 3, c = (idx & 7) << 2;
            cp16(&Asd[r * 36 + c], Ab + (size_t)(bm + r) * K + k0 + c);
        }
#pragma unroll
        for (int i = 0; i < 6; i++) {               // B: 1536 16B chunks
            int idx = tid + 256 * i;
            int r = idx >> 3, c = (idx & 7) << 2;
            cp16(&Bsd[r * 36 + c], Bb + (size_t)(bn + r) * K + k0 + c);
        }
        cp_commit();
    };

    const int nIter = K / 32;
    issue(0, 0);
    issue(1, 32);

    for (int it = 0; it < nIter; it++) {
        cp_wait<1>();          // oldest group (stage it%3) complete
        __syncthreads();       // everyone done reading stage (it-1)%3 == (it+2)%3

        if (it + 2 < nIter) issue((it + 2) % 3, (it + 2) * 32);
        else                cp_commit();            // empty group keeps ledger

        const float* Asd = dsm + (it % 3) * (320 * 36);
        const float* Bsd = Asd + 128 * 36;
#pragma unroll
        for (int ks = 0; ks < 4; ks++) {
            const int kk = ks * 8;
            uint32_t a[4][4], b[6][2];
#pragma unroll
            for (int mt = 0; mt < 4; mt++) {
                int r = wm * 64 + mt * 16 + g;
                a[mt][0] = U(Asd[r * 36 + kk + t]);
                a[mt][1] = U(Asd[(r + 8) * 36 + kk + t]);
                a[mt][2] = U(Asd[r * 36 + kk + t + 4]);
                a[mt][3] = U(Asd[(r + 8) * 36 + kk + t + 4]);
            }
#pragma unroll
            for (int nt = 0; nt < 6; nt++) {
                int n = wn * 48 + nt * 8 + g;
                b[nt][0] = U(Bsd[n * 36 + kk + t]);
                b[nt][1] = U(Bsd[n * 36 + kk + t + 4]);
            }
#pragma unroll
            for (int mt = 0; mt < 4; mt++)
#pragma unroll
                for (int nt = 0; nt < 6; nt++)
                    mma_tf32(acc[mt][nt], a[mt][0], a[mt][1], a[mt][2], a[mt][3],
                             b[nt][0], b[nt][1]);
        }
    }

    // Epilogue
    if (MODE == 0) {
        // warp cols wn*48 not 64-aligned -> head computed per nt (warp-uniform:
        // each 8-wide nt group never crosses a 64 or 576 boundary).
#pragma unroll
        for (int mt = 0; mt < 4; mt++) {
#pragma unroll
            for (int half = 0; half < 2; half++) {
                int m = bm + wm * 64 + mt * 16 + g + half * 8;
                int b_ = m >> 10, tok = m & 1023;
#pragma unroll
                for (int nt = 0; nt < 6; nt++) {
                    int col = bn + wn * 48 + nt * 8 + t * 2;
                    int which = col / 576;
                    int rem = col - which * 576;
                    int h = rem >> 6, d = rem & 63;
                    float* dst = (which == 0) ? g_q : (which == 1) ? g_k : g_v;
                    float v0 = __uint_as_float(f2tf(acc[mt][nt][half * 2]     + bias[col]));
                    float v1 = __uint_as_float(f2tf(acc[mt][nt][half * 2 + 1] + bias[col + 1]));
                    if (which == 0) { v0 *= 0.125f; v1 *= 0.125f; }   // exact
                    *(float2*)&dst[(((size_t)(b_ * HH + h) << 10) + tok) * HD + d] =
                        make_float2(v0, v1);
                }
            }
        }
    } else {
#pragma unroll
        for (int mt = 0; mt < 4; mt++) {
#pragma unroll
            for (int half = 0; half < 2; half++) {
                int m = bm + wm * 64 + mt * 16 + g + half * 8;
#pragma unroll
                for (int nt = 0; nt < 6; nt++) {
                    int col = bn + wn * 48 + nt * 8 + t * 2;
                    float2 r = make_float2(acc[mt][nt][half * 2]     + bias[col],
                                           acc[mt][nt][half * 2 + 1] + bias[col + 1]);
                    *(float2*)&C[(size_t)m * N + col] = r;
                }
            }
        }
    }
}

// ---------------------------------------------------------------------------
// Flash attention (tensor core): block = 128 queries of one (b,h), KV tiles 32.
// 4 warps (128 threads); each warp owns 32 query rows end-to-end.
// Q/K/V arrive pre-tf32 (Q pre-scaled) -> zero CVT on all MMA operand loads;
// only P is rounded (f2tf) before the PV MMA, matching previous numerics.
// 2-stage cp.async double buffering of K [32][68] and V [32][72] (72%32=8 ->
// PV B-frag bank 8t+g, conflict-free, no transpose).
// smem = (128*68 + 2*32*68 + 2*32*72 + 128*36)*4 = 89088 B -> 2 blocks/SM.
// ---------------------------------------------------------------------------
#define ATTN_SMEM_BYTES ((128*68 + 2*32*68 + 2*32*72 + 128*36) * 4)

__global__ __launch_bounds__(128) void attn_tc()
{
    extern __shared__ char sraw[];
    float (*Qs)[68] = reinterpret_cast<float(*)[68]>(sraw);
    float* KsB = reinterpret_cast<float*>(sraw + 128 * 68 * 4);
    float* VsB = reinterpret_cast<float*>(sraw + (128 * 68 + 2 * 32 * 68) * 4);
    uint32_t (*Ps)[36] = reinterpret_cast<uint32_t(*)[36]>(
        sraw + (128 * 68 + 2 * 32 * 68 + 2 * 32 * 72) * 4);

    const int tid  = threadIdx.x;
    const int lane = tid & 31;
    const int warp = tid >> 5;                 // 0..3
    const int g = lane >> 2, t = lane & 3;
    const int bh = blockIdx.y;                 // 0..143
    const int q0 = blockIdx.x * 128;
    const int qr = warp * 32;                  // warp's 32 query rows

    const float* Qg = g_q + ((size_t)bh * NN + q0) * HD;
    const float* Kg = g_k + (size_t)bh * NN * HD;
    const float* Vg = g_v + (size_t)bh * NN * HD;

    auto issue = [&](int stage, int kt) {
        float* Kd = KsB + stage * 32 * 68;
        float* Vd = VsB + stage * 32 * 72;
#pragma unroll
        for (int i = 0; i < 4; i++) {
            int idx = tid + 128 * i;
            int r = idx >> 4, c = (idx & 15) << 2;
            cp16(&Kd[r * 68 + c], Kg + (size_t)(kt + r) * HD + c);
        }
#pragma unroll
        for (int i = 0; i < 4; i++) {
            int idx = tid + 128 * i;
            int r = idx >> 4, c = (idx & 15) << 2;
            cp16(&Vd[r * 72 + c], Vg + (size_t)(kt + r) * HD + c);
        }
        cp_commit();
    };

    issue(0, 0);

    // Q tile: plain copy (already tf32-rounded and 1/8-scaled by gemm0)
#pragma unroll
    for (int i = 0; i < 16; i++) {
        int idx = tid + 128 * i;
        int r = idx >> 4, c = (idx & 15) << 2;
        *(float4*)&Qs[r][c] = ((const float4*)Qg)[idx];
    }

    float m_i[2][2], l_i[2][2], o[2][8][4];
#pragma unroll
    for (int mt = 0; mt < 2; mt++) {
        m_i[mt][0] = -1e30f; m_i[mt][1] = -1e30f;
        l_i[mt][0] = 0.0f;   l_i[mt][1] = 0.0f;
#pragma unroll
        for (int nt = 0; nt < 8; nt++)
#pragma unroll
            for (int i = 0; i < 4; i++) o[mt][nt][i] = 0.0f;
    }

    const int nIter = NN / 32;   // 32
    for (int it = 0; it < nIter; it++) {
        const int stage = it & 1;
        if (it + 1 < nIter) {
            issue(stage ^ 1, (it + 1) * 32);
            cp_wait<1>();
        } else {
            cp_wait<0>();
        }
        __syncthreads();

        const float* Kd = KsB + stage * 32 * 68;
        const float* Vd = VsB + stage * 32 * 72;

        // S[32x32] = Q(warp rows) @ K^T
        float s[2][4][4];
#pragma unroll
        for (int mt = 0; mt < 2; mt++)
#pragma unroll
            for (int nt = 0; nt < 4; nt++)
#pragma unroll
                for (int i = 0; i < 4; i++) s[mt][nt][i] = 0.0f;

#pragma unroll
        for (int ks = 0; ks < 8; ks++) {
            const int kk = ks * 8;
            uint32_t a[2][4], b[4][2];
#pragma unroll
            for (int mt = 0; mt < 2; mt++) {
                int r = qr + mt * 16 + g;
                a[mt][0] = U(Qs[r][kk + t]);
                a[mt][1] = U(Qs[r + 8][kk + t]);
                a[mt][2] = U(Qs[r][kk + t + 4]);
                a[mt][3] = U(Qs[r + 8][kk + t + 4]);
            }
#pragma unroll
            for (int nt = 0; nt < 4; nt++) {
                int n = nt * 8 + g;
                b[nt][0] = U(Kd[n * 68 + kk + t]);
                b[nt][1] = U(Kd[n * 68 + kk + t + 4]);
            }
#pragma unroll
            for (int mt = 0; mt < 2; mt++)
#pragma unroll
                for (int nt = 0; nt < 4; nt++)
                    mma_tf32(s[mt][nt], a[mt][0], a[mt][1], a[mt][2], a[mt][3],
                             b[nt][0], b[nt][1]);
        }

        // Online softmax per mt: rows r0 = qr+mt*16+g (elems 0,1), r1 = r0+8 (2,3)
#pragma unroll
        for (int mt = 0; mt < 2; mt++) {
            float mt0 = -1e30f, mt1 = -1e30f;
#pragma unroll
            for (int nt = 0; nt < 4; nt++) {
                mt0 = fmaxf(mt0, fmaxf(s[mt][nt][0], s[mt][nt][1]));
                mt1 = fmaxf(mt1, fmaxf(s[mt][nt][2], s[mt][nt][3]));
            }
            mt0 = fmaxf(mt0, __shfl_xor_sync(0xffffffffu, mt0, 1));
            mt0 = fmaxf(mt0, __shfl_xor_sync(0xffffffffu, mt0, 2));
            mt1 = fmaxf(mt1, __shfl_xor_sync(0xffffffffu, mt1, 1));
            mt1 = fmaxf(mt1, __shfl_xor_sync(0xffffffffu, mt1, 2));

            float mn0 = fmaxf(m_i[mt][0], mt0), mn1 = fmaxf(m_i[mt][1], mt1);
            float c0 = __expf(m_i[mt][0] - mn0), c1 = __expf(m_i[mt][1] - mn1);
            m_i[mt][0] = mn0; m_i[mt][1] = mn1;

            float rs0 = 0.0f, rs1 = 0.0f;
            const int r0 = qr + mt * 16 + g;
#pragma unroll
            for (int nt = 0; nt < 4; nt++) {
                float p00 = __expf(s[mt][nt][0] - mn0);
                float p01 = __expf(s[mt][nt][1] - mn0);
                float p10 = __expf(s[mt][nt][2] - mn1);
                float p11 = __expf(s[mt][nt][3] - mn1);
                rs0 += p00 + p01;
                rs1 += p10 + p11;
                int col = nt * 8 + t * 2;
                *(uint2*)&Ps[r0][col]     = make_uint2(f2tf(p00), f2tf(p01));
                *(uint2*)&Ps[r0 + 8][col] = make_uint2(f2tf(p10), f2tf(p11));
            }
            rs0 += __shfl_xor_sync(0xffffffffu, rs0, 1);
            rs0 += __shfl_xor_sync(0xffffffffu, rs0, 2);
            rs1 += __shfl_xor_sync(0xffffffffu, rs1, 1);
            rs1 += __shfl_xor_sync(0xffffffffu, rs1, 2);
            l_i[mt][0] = l_i[mt][0] * c0 + rs0;
            l_i[mt][1] = l_i[mt][1] * c1 + rs1;
#pragma unroll
            for (int nt = 0; nt < 8; nt++) {
                o[mt][nt][0] *= c0; o[mt][nt][1] *= c0;
                o[mt][nt][2] *= c1; o[mt][nt][3] *= c1;
            }
        }
        __syncwarp();   // Ps rows are warp-private

        // O[32x64] += P[32x32] @ V[32x64]
#pragma unroll
        for (int ks = 0; ks < 4; ks++) {
            const int kk = ks * 8;
            uint32_t a[2][4], b[8][2];
#pragma unroll
            for (int mt = 0; mt < 2; mt++) {
                int r = qr + mt * 16 + g;
                a[mt][0] = Ps[r][kk + t];
                a[mt][1] = Ps[r + 8][kk + t];
                a[mt][2] = Ps[r][kk + t + 4];
                a[mt][3] = Ps[r + 8][kk + t + 4];
            }
#pragma unroll
            for (int nt = 0; nt < 8; nt++) {
                int n = nt * 8 + g;
                b[nt][0] = U(Vd[(kk + t) * 72 + n]);
                b[nt][1] = U(Vd[(kk + t + 4) * 72 + n]);
            }
#pragma unroll
            for (int mt = 0; mt < 2; mt++)
#pragma unroll
                for (int nt = 0; nt < 8; nt++)
                    mma_tf32(o[mt][nt], a[mt][0], a[mt][1], a[mt][2], a[mt][3],
                             b[nt][0], b[nt][1]);
        }
        __syncthreads();   // all reads of this K/V stage done before refill
    }

    // Epilogue: normalize, round to tf32 (gemm1 operand), write g_att [B,N,H*HD]
    const int b_ = bh / HH;
    const int h  = bh - b_ * HH;
#pragma unroll
    for (int mt = 0; mt < 2; mt++) {
        const float inv0 = 1.0f / l_i[mt][0];
        const float inv1 = 1.0f / l_i[mt][1];
        const int tok0 = q0 + qr + mt * 16 + g;
        const int tok1 = tok0 + 8;
        float* p0 = g_att + (size_t)(b_ * NN + tok0) * ATT_N + h * HD;
        float* p1 = g_att + (size_t)(b_ * NN + tok1) * ATT_N + h * HD;
#pragma unroll
        for (int nt = 0; nt < 8; nt++) {
            int d = nt * 8 + t * 2;
            *(float2*)(p0 + d) = make_float2(__uint_as_float(f2tf(o[mt][nt][0] * inv0)),
                                             __uint_as_float(f2tf(o[mt][nt][1] * inv0)));
            *(float2*)(p1 + d) = make_float2(__uint_as_float(f2tf(o[mt][nt][2] * inv1)),
                                             __uint_as_float(f2tf(o[mt][nt][3] * inv1)));
        }
    }
}

// ---------------------------------------------------------------------------
extern "C" void kernel_launch(void* const* d_in, const int* in_sizes, int n_in,
                              void* d_out, int out_size)
{
    const float* x      = (const float*)d_in[0];
    const float* qkv_w  = (const float*)d_in[1];
    const float* qkv_b  = (const float*)d_in[2];
    const float* proj_w = (const float*)d_in[3];
    const float* proj_b = (const float*)d_in[4];
    float* out = (float*)d_out;

    cudaFuncSetAttribute(gemm_tc<0>, cudaFuncAttributeMaxDynamicSharedMemorySize,
                         GEMM_SMEM_BYTES);
    cudaFuncSetAttribute(gemm_tc<1>, cudaFuncAttributeMaxDynamicSharedMemorySize,
                         GEMM_SMEM_BYTES);
    cudaFuncSetAttribute(attn_tc, cudaFuncAttributeMaxDynamicSharedMemorySize,
                         ATTN_SMEM_BYTES);

    // 0) Pre-round MMA operands to tf32 in global memory
    cvt_tf32<0><<<(M_TOK * CC / 4 + 255) / 256, 256>>>(x, M_TOK * CC / 4);
    cvt_tf32<1><<<(QKV_N * CC / 4 + 255) / 256, 256>>>(qkv_w, QKV_N * CC / 4);
    cvt_tf32<2><<<(CC * ATT_N / 4 + 255) / 256, 256>>>(proj_w, CC * ATT_N / 4);

    // 1) QKV projection + bias -> tf32-rounded q/k/v (q pre-scaled by 1/8)
    dim3 g1(M_TOK / 128, QKV_N / 192);
    gemm_tc<0><<<g1, 256, GEMM_SMEM_BYTES>>>(qkv_b, nullptr, M_TOK, QKV_N, CC);

    // 2) Flash attention -> g_att [B,N,H*HD] (tf32-rounded)
    dim3 g2(NN / 128, BB * HH);
    attn_tc<<<g2, 128, ATTN_SMEM_BYTES>>>();

    // 3) Output projection + bias (exact f32 output)
    dim3 g3(M_TOK / 128, CC / 192);
    gemm_tc<1><<<g3, 256, GEMM_SMEM_BYTES>>>(proj_b, out, M_TOK, CC, ATT_N);
}

// round 11
// speedup vs baseline: 2.4025x; 1.6038x over previous
#include <cuda_runtime.h>
#include <cuda_fp16.h>
#include <cstdint>

#define BB 16
#define NN 1024
#define CC 768
#define HH 9
#define HD 64
#define M_TOK (BB * NN)        // 16384
#define QKV_N (3 * HH * HD)    // 1728
#define ATT_N (HH * HD)        // 576

// Scratch (device globals — no allocation allowed). All fp16 operands.
__device__ __half g_q[BB * HH * NN * HD];    // [B,H,N,HD], pre-scaled by 1/8
__device__ __half g_k[BB * HH * NN * HD];
__device__ __half g_v[BB * HH * NN * HD];    // [B,H,N,HD] (row = key, col = d)
__device__ __half g_att[M_TOK * ATT_N];      // [B,N,H*HD]
__device__ __half g_xt[M_TOK * CC];          // fp16 copies of inputs
__device__ __half g_wqkv[QKV_N * CC];
__device__ __half g_wproj[CC * ATT_N];

// ---------------------------------------------------------------------------
// Helpers
// ---------------------------------------------------------------------------
__device__ __forceinline__ uint32_t f2h2(float a, float b) {
    __half2 h = __floats2half2_rn(a, b);
    return *(uint32_t*)&h;
}

__device__ __forceinline__ void cp16(void* smem_dst, const void* gmem_src) {
    uint32_t sa = (uint32_t)__cvta_generic_to_shared(smem_dst);
    asm volatile("cp.async.cg.shared.global [%0], [%1], 16;"
                 :: "r"(sa), "l"(gmem_src));
}
__device__ __forceinline__ void cp_commit() {
    asm volatile("cp.async.commit_group;");
}
template <int N>
__device__ __forceinline__ void cp_wait() {
    asm volatile("cp.async.wait_group %0;" :: "n"(N));
}

// D(16x8,f32) += A(16x16,f16,row) * B(16x8,f16,col)
__device__ __forceinline__ void mma_f16(float* d,
    uint32_t a0, uint32_t a1, uint32_t a2, uint32_t a3,
    uint32_t b0, uint32_t b1)
{
    asm volatile(
        "mma.sync.aligned.m16n8k16.row.col.f32.f16.f16.f32 "
        "{%0,%1,%2,%3}, {%4,%5,%6,%7}, {%8,%9}, {%0,%1,%2,%3};"
        : "+f"(d[0]), "+f"(d[1]), "+f"(d[2]), "+f"(d[3])
        : "r"(a0), "r"(a1), "r"(a2), "r"(a3), "r"(b0), "r"(b1));
}

// ldmatrix x4 transposed b16 (for V -> PV B-fragments)
__device__ __forceinline__ void ldsm_x4_t(
    uint32_t& r0, uint32_t& r1, uint32_t& r2, uint32_t& r3, const void* p)
{
    uint32_t sa = (uint32_t)__cvta_generic_to_shared(p);
    asm volatile("ldmatrix.sync.aligned.m8n8.x4.trans.shared.b16 "
                 "{%0,%1,%2,%3}, [%4];"
                 : "=r"(r0), "=r"(r1), "=r"(r2), "=r"(r3) : "r"(sa));
}

// ---------------------------------------------------------------------------
// Pre-convert inputs to fp16 in global memory.
// DST: 0 -> g_xt, 1 -> g_wqkv, 2 -> g_wproj. n4 = element count / 4.
// ---------------------------------------------------------------------------
template <int DST>
__global__ __launch_bounds__(256) void cvt_h(const float* __restrict__ src, int n4)
{
    __half* dst = (DST == 0) ? g_xt : (DST == 1) ? g_wqkv : g_wproj;
    int i = blockIdx.x * 256 + threadIdx.x;
    if (i < n4) {
        float4 v = ((const float4*)src)[i];
        uint2 r = make_uint2(f2h2(v.x, v.y), f2h2(v.z, v.w));
        ((uint2*)dst)[i] = r;
    }
}

// ---------------------------------------------------------------------------
// GEMM (fp16 tensor core): C[M,N] = A[M,K] @ B[N,K]^T + bias.
// Block 128x192, BK=32 halves, 256 threads = 8 warps 2(M)x4(N), warp 64x48.
// Per BK: 2 x m16n8k16 k-chunks. smem rows stored as half2-pairs (uint32),
// stride 20 u32 -> frag bank = 20g + t, distinct over all 32 lanes.
// 3-stage cp.async ring, ONE __syncthreads per k-iter.
// MODE 0: A=g_xt, B=g_wqkv -> scatter fp16 into g_q (x0.125)/g_k/g_v.
// MODE 1: A=g_att, B=g_wproj -> f32 store + bias.
// ---------------------------------------------------------------------------
#define GEMM_SMEM_BYTES (3 * (128 + 192) * 20 * 4)   // 76800

template <int MODE>
__global__ __launch_bounds__(256) void gemm_tc(
    const float* __restrict__ bias, float* __restrict__ C,
    int M, int N, int K)
{
    extern __shared__ uint32_t dsm[];

    const int tid  = threadIdx.x;
    const int lane = tid & 31;
    const int warp = tid >> 5;          // 0..7
    const int wm = warp >> 2;           // 0..1  (M groups of 64)
    const int wn = warp & 3;            // 0..3  (N groups of 48)
    const int g = lane >> 2, t = lane & 3;
    const int bm = blockIdx.x * 128;
    const int bn = blockIdx.y * 192;

    const __half* Ah = (MODE == 0) ? g_xt  : g_att;
    const __half* Bh = (MODE == 0) ? g_wqkv : g_wproj;

    float acc[4][6][4];
#pragma unroll
    for (int mt = 0; mt < 4; mt++)
#pragma unroll
        for (int nt = 0; nt < 6; nt++)
#pragma unroll
            for (int i = 0; i < 4; i++) acc[mt][nt][i] = 0.0f;

    // Stage s: A tile (128 rows x 20 u32) then B tile (192 x 20)
    auto issue = [&](int stage, int k0) {
        uint32_t* Asd = dsm + stage * (320 * 20);
        uint32_t* Bsd = Asd + 128 * 20;
#pragma unroll
        for (int i = 0; i < 2; i++) {               // A: 512 16B chunks
            int idx = tid + 256 * i;
            int r = idx >> 2, c = idx & 3;
            cp16(&Asd[r * 20 + c * 4], Ah + (size_t)(bm + r) * K + k0 + c * 8);
        }
#pragma unroll
        for (int i = 0; i < 3; i++) {               // B: 768 16B chunks
            int idx = tid + 256 * i;
            int r = idx >> 2, c = idx & 3;
            cp16(&Bsd[r * 20 + c * 4], Bh + (size_t)(bn + r) * K + k0 + c * 8);
        }
        cp_commit();
    };

    const int nIter = K / 32;
    issue(0, 0);
    issue(1, 32);

    for (int it = 0; it < nIter; it++) {
        cp_wait<1>();
        __syncthreads();

        if (it + 2 < nIter) issue((it + 2) % 3, (it + 2) * 32);
        else                cp_commit();            // keep wait-ledger counting

        const uint32_t* Asd = dsm + (it % 3) * (320 * 20);
        const uint32_t* Bsd = Asd + 128 * 20;
#pragma unroll
        for (int ks = 0; ks < 2; ks++) {            // two k16 chunks per BK=32
            const int kk = ks * 8;                  // half2-pair index
            uint32_t a[4][4], b[6][2];
#pragma unroll
            for (int mt = 0; mt < 4; mt++) {
                int r = wm * 64 + mt * 16 + g;
                a[mt][0] = Asd[r * 20 + kk + t];
                a[mt][1] = Asd[(r + 8) * 20 + kk + t];
                a[mt][2] = Asd[r * 20 + kk + t + 4];
                a[mt][3] = Asd[(r + 8) * 20 + kk + t + 4];
            }
#pragma unroll
            for (int nt = 0; nt < 6; nt++) {
                int n = wn * 48 + nt * 8 + g;
                b[nt][0] = Bsd[n * 20 + kk + t];
                b[nt][1] = Bsd[n * 20 + kk + t + 4];
            }
#pragma unroll
            for (int mt = 0; mt < 4; mt++)
#pragma unroll
                for (int nt = 0; nt < 6; nt++)
                    mma_f16(acc[mt][nt], a[mt][0], a[mt][1], a[mt][2], a[mt][3],
                            b[nt][0], b[nt][1]);
        }
    }

    // Epilogue
    if (MODE == 0) {
#pragma unroll
        for (int mt = 0; mt < 4; mt++) {
#pragma unroll
            for (int half = 0; half < 2; half++) {
                int m = bm + wm * 64 + mt * 16 + g + half * 8;
                int b_ = m >> 10, tok = m & 1023;
#pragma unroll
                for (int nt = 0; nt < 6; nt++) {
                    int col = bn + wn * 48 + nt * 8 + t * 2;
                    int which = col / 576;
                    int rem = col - which * 576;
                    int h = rem >> 6, d = rem & 63;
                    __half* dst = (which == 0) ? g_q : (which == 1) ? g_k : g_v;
                    float v0 = acc[mt][nt][half * 2]     + bias[col];
                    float v1 = acc[mt][nt][half * 2 + 1] + bias[col + 1];
                    if (which == 0) { v0 *= 0.125f; v1 *= 0.125f; }   // exact
                    *(uint32_t*)&dst[(((size_t)(b_ * HH + h) << 10) + tok) * HD + d] =
                        f2h2(v0, v1);
                }
            }
        }
    } else {
#pragma unroll
        for (int mt = 0; mt < 4; mt++) {
#pragma unroll
            for (int half = 0; half < 2; half++) {
                int m = bm + wm * 64 + mt * 16 + g + half * 8;
#pragma unroll
                for (int nt = 0; nt < 6; nt++) {
                    int col = bn + wn * 48 + nt * 8 + t * 2;
                    float2 r = make_float2(acc[mt][nt][half * 2]     + bias[col],
                                           acc[mt][nt][half * 2 + 1] + bias[col + 1]);
                    *(float2*)&C[(size_t)m * N + col] = r;
                }
            }
        }
    }
}

// ---------------------------------------------------------------------------
// Flash attention (fp16 tensor core): block = 128 queries of one (b,h),
// KV tiles 32. 4 warps; each owns 32 query rows. fp32 softmax.
// smem (u32 units): Qs[128][36] | K 2x[32][36] | V 2x[32][36] | Ps[128][20]
//   = 47104 B -> 4 blocks/SM.
// Q/K frag loads direct (stride 36 -> banks 4g-quads + t, conflict-free).
// V kept row-major [key][d]; PV B-frags via ldmatrix.x4.trans (row stride
// 144 B -> 8 row-addresses hit distinct bank quads).
// ---------------------------------------------------------------------------
#define ATTN_SMEM_BYTES ((128*36 + 2*32*36 + 2*32*36 + 128*20) * 4)  // 47104

__global__ __launch_bounds__(128) void attn_tc()
{
    extern __shared__ uint32_t smu[];
    uint32_t* Qs  = smu;                         // [128][36]
    uint32_t* KsB = smu + 128 * 36;              // 2 x [32][36]
    uint32_t* VsB = KsB + 2 * 32 * 36;           // 2 x [32][36]
    uint32_t* Ps  = VsB + 2 * 32 * 36;           // [128][20]

    const int tid  = threadIdx.x;
    const int lane = tid & 31;
    const int warp = tid >> 5;                 // 0..3
    const int g = lane >> 2, t = lane & 3;
    const int bh = blockIdx.y;                 // 0..143
    const int q0 = blockIdx.x * 128;
    const int qr = warp * 32;                  // warp's 32 query rows

    const __half* Qg = g_q + ((size_t)bh * NN + q0) * HD;
    const __half* Kg = g_k + (size_t)bh * NN * HD;
    const __half* Vg = g_v + (size_t)bh * NN * HD;

    auto issue = [&](int stage, int kt) {
        uint32_t* Kd = KsB + stage * 32 * 36;
        uint32_t* Vd = VsB + stage * 32 * 36;
#pragma unroll
        for (int i = 0; i < 2; i++) {            // K: 256 16B chunks
            int idx = tid + 128 * i;
            int r = idx >> 3, c = idx & 7;
            cp16(&Kd[r * 36 + c * 4], Kg + (size_t)(kt + r) * HD + c * 8);
        }
#pragma unroll
        for (int i = 0; i < 2; i++) {            // V: 256 16B chunks
            int idx = tid + 128 * i;
            int r = idx >> 3, c = idx & 7;
            cp16(&Vd[r * 36 + c * 4], Vg + (size_t)(kt + r) * HD + c * 8);
        }
        cp_commit();
    };

    issue(0, 0);

    // Q tile copy (already fp16, pre-scaled): 1024 uint4
#pragma unroll
    for (int i = 0; i < 8; i++) {
        int idx = tid + 128 * i;
        int r = idx >> 3, c = idx & 7;
        *(uint4*)&Qs[r * 36 + c * 4] = ((const uint4*)Qg)[idx];
    }

    float m_i[2][2], l_i[2][2], o[2][8][4];
#pragma unroll
    for (int mt = 0; mt < 2; mt++) {
        m_i[mt][0] = -1e30f; m_i[mt][1] = -1e30f;
        l_i[mt][0] = 0.0f;   l_i[mt][1] = 0.0f;
#pragma unroll
        for (int nt = 0; nt < 8; nt++)
#pragma unroll
            for (int i = 0; i < 4; i++) o[mt][nt][i] = 0.0f;
    }

    const int nIter = NN / 32;   // 32
    for (int it = 0; it < nIter; it++) {
        const int stage = it & 1;
        if (it + 1 < nIter) {
            issue(stage ^ 1, (it + 1) * 32);
            cp_wait<1>();
        } else {
            cp_wait<0>();
        }
        __syncthreads();

        const uint32_t* Kd = KsB + stage * 32 * 36;
        const uint32_t* Vd = VsB + stage * 32 * 36;

        // S[32x32] = Q(warp rows) @ K^T : HD=64 -> 4 k16 chunks
        float s[2][4][4];
#pragma unroll
        for (int mt = 0; mt < 2; mt++)
#pragma unroll
            for (int nt = 0; nt < 4; nt++)
#pragma unroll
                for (int i = 0; i < 4; i++) s[mt][nt][i] = 0.0f;

#pragma unroll
        for (int ks = 0; ks < 4; ks++) {
            const int kk = ks * 8;               // half2-pair index into d
            uint32_t a[2][4], b[4][2];
#pragma unroll
            for (int mt = 0; mt < 2; mt++) {
                int r = qr + mt * 16 + g;
                a[mt][0] = Qs[r * 36 + kk + t];
                a[mt][1] = Qs[(r + 8) * 36 + kk + t];
                a[mt][2] = Qs[r * 36 + kk + t + 4];
                a[mt][3] = Qs[(r + 8) * 36 + kk + t + 4];
            }
#pragma unroll
            for (int nt = 0; nt < 4; nt++) {
                int n = nt * 8 + g;
                b[nt][0] = Kd[n * 36 + kk + t];
                b[nt][1] = Kd[n * 36 + kk + t + 4];
            }
#pragma unroll
            for (int mt = 0; mt < 2; mt++)
#pragma unroll
                for (int nt = 0; nt < 4; nt++)
                    mma_f16(s[mt][nt], a[mt][0], a[mt][1], a[mt][2], a[mt][3],
                            b[nt][0], b[nt][1]);
        }

        // Online softmax per mt: rows r0 = qr+mt*16+g (elems 0,1), r1 = r0+8
#pragma unroll
        for (int mt = 0; mt < 2; mt++) {
            float mt0 = -1e30f, mt1 = -1e30f;
#pragma unroll
            for (int nt = 0; nt < 4; nt++) {
                mt0 = fmaxf(mt0, fmaxf(s[mt][nt][0], s[mt][nt][1]));
                mt1 = fmaxf(mt1, fmaxf(s[mt][nt][2], s[mt][nt][3]));
            }
            mt0 = fmaxf(mt0, __shfl_xor_sync(0xffffffffu, mt0, 1));
            mt0 = fmaxf(mt0, __shfl_xor_sync(0xffffffffu, mt0, 2));
            mt1 = fmaxf(mt1, __shfl_xor_sync(0xffffffffu, mt1, 1));
            mt1 = fmaxf(mt1, __shfl_xor_sync(0xffffffffu, mt1, 2));

            float mn0 = fmaxf(m_i[mt][0], mt0), mn1 = fmaxf(m_i[mt][1], mt1);
            float c0 = __expf(m_i[mt][0] - mn0), c1 = __expf(m_i[mt][1] - mn1);
            m_i[mt][0] = mn0; m_i[mt][1] = mn1;

            float rs0 = 0.0f, rs1 = 0.0f;
            const int r0 = qr + mt * 16 + g;
#pragma unroll
            for (int nt = 0; nt < 4; nt++) {
                float p00 = __expf(s[mt][nt][0] - mn0);
                float p01 = __expf(s[mt][nt][1] - mn0);
                float p10 = __expf(s[mt][nt][2] - mn1);
                float p11 = __expf(s[mt][nt][3] - mn1);
                rs0 += p00 + p01;
                rs1 += p10 + p11;
                int pp = nt * 4 + t;              // half2-pair index (cols nt*8+2t)
                Ps[r0 * 20 + pp]       = f2h2(p00, p01);
                Ps[(r0 + 8) * 20 + pp] = f2h2(p10, p11);
            }
            rs0 += __shfl_xor_sync(0xffffffffu, rs0, 1);
            rs0 += __shfl_xor_sync(0xffffffffu, rs0, 2);
            rs1 += __shfl_xor_sync(0xffffffffu, rs1, 1);
            rs1 += __shfl_xor_sync(0xffffffffu, rs1, 2);
            l_i[mt][0] = l_i[mt][0] * c0 + rs0;
            l_i[mt][1] = l_i[mt][1] * c1 + rs1;
#pragma unroll
            for (int nt = 0; nt < 8; nt++) {
                o[mt][nt][0] *= c0; o[mt][nt][1] *= c0;
                o[mt][nt][2] *= c1; o[mt][nt][3] *= c1;
            }
        }
        __syncwarp();   // Ps rows are warp-private

        // O[32x64] += P[32x32] @ V[32x64] : 2 k16 chunks, V via ldmatrix.trans
#pragma unroll
        for (int ks = 0; ks < 2; ks++) {
            const int kk = ks * 8;
            uint32_t a[2][4];
#pragma unroll
            for (int mt = 0; mt < 2; mt++) {
                int r = qr + mt * 16 + g;
                a[mt][0] = Ps[r * 20 + kk + t];
                a[mt][1] = Ps[(r + 8) * 20 + kk + t];
                a[mt][2] = Ps[r * 20 + kk + t + 4];
                a[mt][3] = Ps[(r + 8) * 20 + kk + t + 4];
            }
            const int krow = ks * 16 + (lane & 15);        // key row for ldmatrix
            const int nbase = ((lane >> 4) << 3);          // 0 or 8
#pragma unroll
            for (int ntp = 0; ntp < 4; ntp++) {
                uint32_t b0, b1, b2, b3;
                int ncol = ntp * 16 + nbase;               // d column (halves)
                ldsm_x4_t(b0, b1, b2, b3, &Vd[krow * 36 + (ncol >> 1)]);
#pragma unroll
                for (int mt = 0; mt < 2; mt++) {
                    mma_f16(o[mt][2 * ntp],     a[mt][0], a[mt][1], a[mt][2], a[mt][3], b0, b1);
                    mma_f16(o[mt][2 * ntp + 1], a[mt][0], a[mt][1], a[mt][2], a[mt][3], b2, b3);
                }
            }
        }
        __syncthreads();   // all reads of this K/V stage done before refill
    }

    // Epilogue: normalize, write fp16 g_att [B,N,H*HD]
    const int b_ = bh / HH;
    const int h  = bh - b_ * HH;
#pragma unroll
    for (int mt = 0; mt < 2; mt++) {
        const float inv0 = 1.0f / l_i[mt][0];
        const float inv1 = 1.0f / l_i[mt][1];
        const int tok0 = q0 + qr + mt * 16 + g;
        const int tok1 = tok0 + 8;
        __half* p0 = g_att + (size_t)(b_ * NN + tok0) * ATT_N + h * HD;
        __half* p1 = g_att + (size_t)(b_ * NN + tok1) * ATT_N + h * HD;
#pragma unroll
        for (int nt = 0; nt < 8; nt++) {
            int d = nt * 8 + t * 2;
            *(uint32_t*)(p0 + d) = f2h2(o[mt][nt][0] * inv0, o[mt][nt][1] * inv0);
            *(uint32_t*)(p1 + d) = f2h2(o[mt][nt][2] * inv1, o[mt][nt][3] * inv1);
        }
    }
}

// ---------------------------------------------------------------------------
extern "C" void kernel_launch(void* const* d_in, const int* in_sizes, int n_in,
                              void* d_out, int out_size)
{
    const float* x      = (const float*)d_in[0];
    const float* qkv_w  = (const float*)d_in[1];
    const float* qkv_b  = (const float*)d_in[2];
    const float* proj_w = (const float*)d_in[3];
    const float* proj_b = (const float*)d_in[4];
    float* out = (float*)d_out;

    cudaFuncSetAttribute(gemm_tc<0>, cudaFuncAttributeMaxDynamicSharedMemorySize,
                         GEMM_SMEM_BYTES);
    cudaFuncSetAttribute(gemm_tc<1>, cudaFuncAttributeMaxDynamicSharedMemorySize,
                         GEMM_SMEM_BYTES);
    cudaFuncSetAttribute(attn_tc, cudaFuncAttributeMaxDynamicSharedMemorySize,
                         ATTN_SMEM_BYTES);

    // 0) Pre-convert MMA operands to fp16 in global memory
    cvt_h<0><<<(M_TOK * CC / 4 + 255) / 256, 256>>>(x, M_TOK * CC / 4);
    cvt_h<1><<<(QKV_N * CC / 4 + 255) / 256, 256>>>(qkv_w, QKV_N * CC / 4);
    cvt_h<2><<<(CC * ATT_N / 4 + 255) / 256, 256>>>(proj_w, CC * ATT_N / 4);

    // 1) QKV projection + bias -> fp16 q/k/v (q pre-scaled by 1/8)
    dim3 g1(M_TOK / 128, QKV_N / 192);
    gemm_tc<0><<<g1, 256, GEMM_SMEM_BYTES>>>(qkv_b, nullptr, M_TOK, QKV_N, CC);

    // 2) Flash attention -> fp16 g_att [B,N,H*HD]
    dim3 g2(NN / 128, BB * HH);
    attn_tc<<<g2, 128, ATTN_SMEM_BYTES>>>();

    // 3) Output projection + bias (f32 output)
    dim3 g3(M_TOK / 128, CC / 192);
    gemm_tc<1><<<g3, 256, GEMM_SMEM_BYTES>>>(proj_b, out, M_TOK, CC, ATT_N);
}

// round 12
// speedup vs baseline: 2.4286x; 1.0109x over previous
#include <cuda_runtime.h>
#include <cuda_fp16.h>
#include <cstdint>

#define BB 16
#define NN 1024
#define CC 768
#define HH 9
#define HD 64
#define M_TOK (BB * NN)        // 16384
#define QKV_N (3 * HH * HD)    // 1728
#define ATT_N (HH * HD)        // 576

// Scratch (device globals — no allocation allowed). All fp16 operands.
__device__ __half g_q[BB * HH * NN * HD];    // [B,H,N,HD], pre-scaled by 1/8
__device__ __half g_k[BB * HH * NN * HD];
__device__ __half g_v[BB * HH * NN * HD];    // [B,H,N,HD] (row = key, col = d)
__device__ __half g_att[M_TOK * ATT_N];      // [B,N,H*HD]
__device__ __half g_xt[M_TOK * CC];          // fp16 copies of inputs
__device__ __half g_wqkv[QKV_N * CC];
__device__ __half g_wproj[CC * ATT_N];

// ---------------------------------------------------------------------------
// Helpers
// ---------------------------------------------------------------------------
__device__ __forceinline__ uint32_t f2h2(float a, float b) {
    __half2 h = __floats2half2_rn(a, b);
    return *(uint32_t*)&h;
}

__device__ __forceinline__ void cp16(void* smem_dst, const void* gmem_src) {
    uint32_t sa = (uint32_t)__cvta_generic_to_shared(smem_dst);
    asm volatile("cp.async.cg.shared.global [%0], [%1], 16;"
                 :: "r"(sa), "l"(gmem_src));
}
__device__ __forceinline__ void cp_commit() {
    asm volatile("cp.async.commit_group;");
}
template <int N>
__device__ __forceinline__ void cp_wait() {
    asm volatile("cp.async.wait_group %0;" :: "n"(N));
}

// D(16x8,f32) += A(16x16,f16,row) * B(16x8,f16,col)
__device__ __forceinline__ void mma_f16(float* d,
    uint32_t a0, uint32_t a1, uint32_t a2, uint32_t a3,
    uint32_t b0, uint32_t b1)
{
    asm volatile(
        "mma.sync.aligned.m16n8k16.row.col.f32.f16.f16.f32 "
        "{%0,%1,%2,%3}, {%4,%5,%6,%7}, {%8,%9}, {%0,%1,%2,%3};"
        : "+f"(d[0]), "+f"(d[1]), "+f"(d[2]), "+f"(d[3])
        : "r"(a0), "r"(a1), "r"(a2), "r"(a3), "r"(b0), "r"(b1));
}

// ldmatrix x4 transposed b16 (for V -> PV B-fragments)
__device__ __forceinline__ void ldsm_x4_t(
    uint32_t& r0, uint32_t& r1, uint32_t& r2, uint32_t& r3, const void* p)
{
    uint32_t sa = (uint32_t)__cvta_generic_to_shared(p);
    asm volatile("ldmatrix.sync.aligned.m8n8.x4.trans.shared.b16 "
                 "{%0,%1,%2,%3}, [%4];"
                 : "=r"(r0), "=r"(r1), "=r"(r2), "=r"(r3) : "r"(sa));
}

// ---------------------------------------------------------------------------
// Pre-convert inputs to fp16 in global memory.
// DST: 0 -> g_xt, 1 -> g_wqkv, 2 -> g_wproj. n4 = element count / 4.
// ---------------------------------------------------------------------------
template <int DST>
__global__ __launch_bounds__(256) void cvt_h(const float* __restrict__ src, int n4)
{
    __half* dst = (DST == 0) ? g_xt : (DST == 1) ? g_wqkv : g_wproj;
    int i = blockIdx.x * 256 + threadIdx.x;
    if (i < n4) {
        float4 v = ((const float4*)src)[i];
        uint2 r = make_uint2(f2h2(v.x, v.y), f2h2(v.z, v.w));
        ((uint2*)dst)[i] = r;
    }
}

// ---------------------------------------------------------------------------
// GEMM (fp16 tensor core): C[M,N] = A[M,K] @ B[N,K]^T + bias.
// Block 128x192, BK=32 halves, 512 threads = 16 warps 4(M)x4(N), warp 32x48.
// 16 warps/SM (4 per SMSP) for latency hiding; acc = 48 regs/thread.
// smem rows as half2-pairs (u32), stride 20 -> frag bank = 20g+t, all 32
// lanes distinct (conflict-free). 3-stage cp.async ring, ONE barrier/iter.
// MODE 0: A=g_xt, B=g_wqkv -> scatter fp16 into g_q (x0.125)/g_k/g_v.
// MODE 1: A=g_att, B=g_wproj -> f32 store + bias.
// ---------------------------------------------------------------------------
#define GEMM_SMEM_BYTES (3 * (128 + 192) * 20 * 4)   // 76800

template <int MODE>
__global__ __launch_bounds__(512, 1) void gemm_tc(
    const float* __restrict__ bias, float* __restrict__ C,
    int M, int N, int K)
{
    extern __shared__ uint32_t dsm[];

    const int tid  = threadIdx.x;
    const int lane = tid & 31;
    const int warp = tid >> 5;          // 0..15
    const int wm = warp >> 2;           // 0..3  (M groups of 32)
    const int wn = warp & 3;            // 0..3  (N groups of 48)
    const int g = lane >> 2, t = lane & 3;
    const int bm = blockIdx.x * 128;
    const int bn = blockIdx.y * 192;

    const __half* Ah = (MODE == 0) ? g_xt  : g_att;
    const __half* Bh = (MODE == 0) ? g_wqkv : g_wproj;

    float acc[2][6][4];
#pragma unroll
    for (int mt = 0; mt < 2; mt++)
#pragma unroll
        for (int nt = 0; nt < 6; nt++)
#pragma unroll
            for (int i = 0; i < 4; i++) acc[mt][nt][i] = 0.0f;

    // Stage s: A tile (128 rows x 20 u32) then B tile (192 x 20)
    auto issue = [&](int stage, int k0) {
        uint32_t* Asd = dsm + stage * (320 * 20);
        uint32_t* Bsd = Asd + 128 * 20;
        {                                            // A: 512 16B chunks
            int r = tid >> 2, c = tid & 3;
            cp16(&Asd[r * 20 + c * 4], Ah + (size_t)(bm + r) * K + k0 + c * 8);
        }
        for (int idx = tid; idx < 768; idx += 512) { // B: 768 16B chunks
            int r = idx >> 2, c = idx & 3;
            cp16(&Bsd[r * 20 + c * 4], Bh + (size_t)(bn + r) * K + k0 + c * 8);
        }
        cp_commit();
    };

    const int nIter = K / 32;
    issue(0, 0);
    issue(1, 32);

    for (int it = 0; it < nIter; it++) {
        cp_wait<1>();
        __syncthreads();

        if (it + 2 < nIter) issue((it + 2) % 3, (it + 2) * 32);
        else                cp_commit();            // keep wait-ledger counting

        const uint32_t* Asd = dsm + (it % 3) * (320 * 20);
        const uint32_t* Bsd = Asd + 128 * 20;
#pragma unroll
        for (int ks = 0; ks < 2; ks++) {            // two k16 chunks per BK=32
            const int kk = ks * 8;                  // half2-pair index
            uint32_t a[2][4], b[6][2];
#pragma unroll
            for (int mt = 0; mt < 2; mt++) {
                int r = wm * 32 + mt * 16 + g;
                a[mt][0] = Asd[r * 20 + kk + t];
                a[mt][1] = Asd[(r + 8) * 20 + kk + t];
                a[mt][2] = Asd[r * 20 + kk + t + 4];
                a[mt][3] = Asd[(r + 8) * 20 + kk + t + 4];
            }
#pragma unroll
            for (int nt = 0; nt < 6; nt++) {
                int n = wn * 48 + nt * 8 + g;
                b[nt][0] = Bsd[n * 20 + kk + t];
                b[nt][1] = Bsd[n * 20 + kk + t + 4];
            }
#pragma unroll
            for (int mt = 0; mt < 2; mt++)
#pragma unroll
                for (int nt = 0; nt < 6; nt++)
                    mma_f16(acc[mt][nt], a[mt][0], a[mt][1], a[mt][2], a[mt][3],
                            b[nt][0], b[nt][1]);
        }
    }

    // Epilogue
    if (MODE == 0) {
#pragma unroll
        for (int mt = 0; mt < 2; mt++) {
#pragma unroll
            for (int half = 0; half < 2; half++) {
                int m = bm + wm * 32 + mt * 16 + g + half * 8;
                int b_ = m >> 10, tok = m & 1023;
#pragma unroll
                for (int nt = 0; nt < 6; nt++) {
                    int col = bn + wn * 48 + nt * 8 + t * 2;
                    int which = col / 576;
                    int rem = col - which * 576;
                    int h = rem >> 6, d = rem & 63;
                    __half* dst = (which == 0) ? g_q : (which == 1) ? g_k : g_v;
                    float v0 = acc[mt][nt][half * 2]     + bias[col];
                    float v1 = acc[mt][nt][half * 2 + 1] + bias[col + 1];
                    if (which == 0) { v0 *= 0.125f; v1 *= 0.125f; }   // exact
                    *(uint32_t*)&dst[(((size_t)(b_ * HH + h) << 10) + tok) * HD + d] =
                        f2h2(v0, v1);
                }
            }
        }
    } else {
#pragma unroll
        for (int mt = 0; mt < 2; mt++) {
#pragma unroll
            for (int half = 0; half < 2; half++) {
                int m = bm + wm * 32 + mt * 16 + g + half * 8;
#pragma unroll
                for (int nt = 0; nt < 6; nt++) {
                    int col = bn + wn * 48 + nt * 8 + t * 2;
                    float2 r = make_float2(acc[mt][nt][half * 2]     + bias[col],
                                           acc[mt][nt][half * 2 + 1] + bias[col + 1]);
                    *(float2*)&C[(size_t)m * N + col] = r;
                }
            }
        }
    }
}

// ---------------------------------------------------------------------------
// Flash attention (fp16 tensor core): block = 128 queries of one (b,h),
// KV tiles 32. 4 warps; each owns 32 query rows. fp32 softmax.
// smem (u32 units): Qs[128][36] | K 2x[32][36] | V 2x[32][36] | Ps[128][20]
//   = 47104 B -> 4 blocks/SM.
// Q/K frag loads direct (stride 36 -> conflict-free).
// V row-major [key][d]; PV B-frags via ldmatrix.x4.trans.
// ---------------------------------------------------------------------------
#define ATTN_SMEM_BYTES ((128*36 + 2*32*36 + 2*32*36 + 128*20) * 4)  // 47104

__global__ __launch_bounds__(128) void attn_tc()
{
    extern __shared__ uint32_t smu[];
    uint32_t* Qs  = smu;                         // [128][36]
    uint32_t* KsB = smu + 128 * 36;              // 2 x [32][36]
    uint32_t* VsB = KsB + 2 * 32 * 36;           // 2 x [32][36]
    uint32_t* Ps  = VsB + 2 * 32 * 36;           // [128][20]

    const int tid  = threadIdx.x;
    const int lane = tid & 31;
    const int warp = tid >> 5;                 // 0..3
    const int g = lane >> 2, t = lane & 3;
    const int bh = blockIdx.y;                 // 0..143
    const int q0 = blockIdx.x * 128;
    const int qr = warp * 32;                  // warp's 32 query rows

    const __half* Qg = g_q + ((size_t)bh * NN + q0) * HD;
    const __half* Kg = g_k + (size_t)bh * NN * HD;
    const __half* Vg = g_v + (size_t)bh * NN * HD;

    auto issue = [&](int stage, int kt) {
        uint32_t* Kd = KsB + stage * 32 * 36;
        uint32_t* Vd = VsB + stage * 32 * 36;
#pragma unroll
        for (int i = 0; i < 2; i++) {            // K: 256 16B chunks
            int idx = tid + 128 * i;
            int r = idx >> 3, c = idx & 7;
            cp16(&Kd[r * 36 + c * 4], Kg + (size_t)(kt + r) * HD + c * 8);
        }
#pragma unroll
        for (int i = 0; i < 2; i++) {            // V: 256 16B chunks
            int idx = tid + 128 * i;
            int r = idx >> 3, c = idx & 7;
            cp16(&Vd[r * 36 + c * 4], Vg + (size_t)(kt + r) * HD + c * 8);
        }
        cp_commit();
    };

    issue(0, 0);

    // Q tile copy (already fp16, pre-scaled): 1024 uint4
#pragma unroll
    for (int i = 0; i < 8; i++) {
        int idx = tid + 128 * i;
        int r = idx >> 3, c = idx & 7;
        *(uint4*)&Qs[r * 36 + c * 4] = ((const uint4*)Qg)[idx];
    }

    float m_i[2][2], l_i[2][2], o[2][8][4];
#pragma unroll
    for (int mt = 0; mt < 2; mt++) {
        m_i[mt][0] = -1e30f; m_i[mt][1] = -1e30f;
        l_i[mt][0] = 0.0f;   l_i[mt][1] = 0.0f;
#pragma unroll
        for (int nt = 0; nt < 8; nt++)
#pragma unroll
            for (int i = 0; i < 4; i++) o[mt][nt][i] = 0.0f;
    }

    const int nIter = NN / 32;   // 32
    for (int it = 0; it < nIter; it++) {
        const int stage = it & 1;
        if (it + 1 < nIter) {
            issue(stage ^ 1, (it + 1) * 32);
            cp_wait<1>();
        } else {
            cp_wait<0>();
        }
        __syncthreads();

        const uint32_t* Kd = KsB + stage * 32 * 36;
        const uint32_t* Vd = VsB + stage * 32 * 36;

        // S[32x32] = Q(warp rows) @ K^T : HD=64 -> 4 k16 chunks
        float s[2][4][4];
#pragma unroll
        for (int mt = 0; mt < 2; mt++)
#pragma unroll
            for (int nt = 0; nt < 4; nt++)
#pragma unroll
                for (int i = 0; i < 4; i++) s[mt][nt][i] = 0.0f;

#pragma unroll
        for (int ks = 0; ks < 4; ks++) {
            const int kk = ks * 8;               // half2-pair index into d
            uint32_t a[2][4], b[4][2];
#pragma unroll
            for (int mt = 0; mt < 2; mt++) {
                int r = qr + mt * 16 + g;
                a[mt][0] = Qs[r * 36 + kk + t];
                a[mt][1] = Qs[(r + 8) * 36 + kk + t];
                a[mt][2] = Qs[r * 36 + kk + t + 4];
                a[mt][3] = Qs[(r + 8) * 36 + kk + t + 4];
            }
#pragma unroll
            for (int nt = 0; nt < 4; nt++) {
                int n = nt * 8 + g;
                b[nt][0] = Kd[n * 36 + kk + t];
                b[nt][1] = Kd[n * 36 + kk + t + 4];
            }
#pragma unroll
            for (int mt = 0; mt < 2; mt++)
#pragma unroll
                for (int nt = 0; nt < 4; nt++)
                    mma_f16(s[mt][nt], a[mt][0], a[mt][1], a[mt][2], a[mt][3],
                            b[nt][0], b[nt][1]);
        }

        // Online softmax per mt: rows r0 = qr+mt*16+g (elems 0,1), r1 = r0+8
#pragma unroll
        for (int mt = 0; mt < 2; mt++) {
            float mt0 = -1e30f, mt1 = -1e30f;
#pragma unroll
            for (int nt = 0; nt < 4; nt++) {
                mt0 = fmaxf(mt0, fmaxf(s[mt][nt][0], s[mt][nt][1]));
                mt1 = fmaxf(mt1, fmaxf(s[mt][nt][2], s[mt][nt][3]));
            }
            mt0 = fmaxf(mt0, __shfl_xor_sync(0xffffffffu, mt0, 1));
            mt0 = fmaxf(mt0, __shfl_xor_sync(0xffffffffu, mt0, 2));
            mt1 = fmaxf(mt1, __shfl_xor_sync(0xffffffffu, mt1, 1));
            mt1 = fmaxf(mt1, __shfl_xor_sync(0xffffffffu, mt1, 2));

            float mn0 = fmaxf(m_i[mt][0], mt0), mn1 = fmaxf(m_i[mt][1], mt1);
            float c0 = __expf(m_i[mt][0] - mn0), c1 = __expf(m_i[mt][1] - mn1);
            m_i[mt][0] = mn0; m_i[mt][1] = mn1;

            float rs0 = 0.0f, rs1 = 0.0f;
            const int r0 = qr + mt * 16 + g;
#pragma unroll
            for (int nt = 0; nt < 4; nt++) {
                float p00 = __expf(s[mt][nt][0] - mn0);
                float p01 = __expf(s[mt][nt][1] - mn0);
                float p10 = __expf(s[mt][nt][2] - mn1);
                float p11 = __expf(s[mt][nt][3] - mn1);
                rs0 += p00 + p01;
                rs1 += p10 + p11;
                int pp = nt * 4 + t;              // half2-pair index (cols nt*8+2t)
                Ps[r0 * 20 + pp]       = f2h2(p00, p01);
                Ps[(r0 + 8) * 20 + pp] = f2h2(p10, p11);
            }
            rs0 += __shfl_xor_sync(0xffffffffu, rs0, 1);
            rs0 += __shfl_xor_sync(0xffffffffu, rs0, 2);
            rs1 += __shfl_xor_sync(0xffffffffu, rs1, 1);
            rs1 += __shfl_xor_sync(0xffffffffu, rs1, 2);
            l_i[mt][0] = l_i[mt][0] * c0 + rs0;
            l_i[mt][1] = l_i[mt][1] * c1 + rs1;
#pragma unroll
            for (int nt = 0; nt < 8; nt++) {
                o[mt][nt][0] *= c0; o[mt][nt][1] *= c0;
                o[mt][nt][2] *= c1; o[mt][nt][3] *= c1;
            }
        }
        __syncwarp();   // Ps rows are warp-private

        // O[32x64] += P[32x32] @ V[32x64] : 2 k16 chunks, V via ldmatrix.trans
#pragma unroll
        for (int ks = 0; ks < 2; ks++) {
            const int kk = ks * 8;
            uint32_t a[2][4];
#pragma unroll
            for (int mt = 0; mt < 2; mt++) {
                int r = qr + mt * 16 + g;
                a[mt][0] = Ps[r * 20 + kk + t];
                a[mt][1] = Ps[(r + 8) * 20 + kk + t];
                a[mt][2] = Ps[r * 20 + kk + t + 4];
                a[mt][3] = Ps[(r + 8) * 20 + kk + t + 4];
            }
            const int krow = ks * 16 + (lane & 15);        // key row for ldmatrix
            const int nbase = ((lane >> 4) << 3);          // 0 or 8
#pragma unroll
            for (int ntp = 0; ntp < 4; ntp++) {
                uint32_t b0, b1, b2, b3;
                int ncol = ntp * 16 + nbase;               // d column (halves)
                ldsm_x4_t(b0, b1, b2, b3, &Vd[krow * 36 + (ncol >> 1)]);
#pragma unroll
                for (int mt = 0; mt < 2; mt++) {
                    mma_f16(o[mt][2 * ntp],     a[mt][0], a[mt][1], a[mt][2], a[mt][3], b0, b1);
                    mma_f16(o[mt][2 * ntp + 1], a[mt][0], a[mt][1], a[mt][2], a[mt][3], b2, b3);
                }
            }
        }
        __syncthreads();   // all reads of this K/V stage done before refill
    }

    // Epilogue: normalize, write fp16 g_att [B,N,H*HD]
    const int b_ = bh / HH;
    const int h  = bh - b_ * HH;
#pragma unroll
    for (int mt = 0; mt < 2; mt++) {
        const float inv0 = 1.0f / l_i[mt][0];
        const float inv1 = 1.0f / l_i[mt][1];
        const int tok0 = q0 + qr + mt * 16 + g;
        const int tok1 = tok0 + 8;
        __half* p0 = g_att + (size_t)(b_ * NN + tok0) * ATT_N + h * HD;
        __half* p1 = g_att + (size_t)(b_ * NN + tok1) * ATT_N + h * HD;
#pragma unroll
        for (int nt = 0; nt < 8; nt++) {
            int d = nt * 8 + t * 2;
            *(uint32_t*)(p0 + d) = f2h2(o[mt][nt][0] * inv0, o[mt][nt][1] * inv0);
            *(uint32_t*)(p1 + d) = f2h2(o[mt][nt][2] * inv1, o[mt][nt][3] * inv1);
        }
    }
}

// ---------------------------------------------------------------------------
extern "C" void kernel_launch(void* const* d_in, const int* in_sizes, int n_in,
                              void* d_out, int out_size)
{
    const float* x      = (const float*)d_in[0];
    const float* qkv_w  = (const float*)d_in[1];
    const float* qkv_b  = (const float*)d_in[2];
    const float* proj_w = (const float*)d_in[3];
    const float* proj_b = (const float*)d_in[4];
    float* out = (float*)d_out;

    cudaFuncSetAttribute(gemm_tc<0>, cudaFuncAttributeMaxDynamicSharedMemorySize,
                         GEMM_SMEM_BYTES);
    cudaFuncSetAttribute(gemm_tc<1>, cudaFuncAttributeMaxDynamicSharedMemorySize,
                         GEMM_SMEM_BYTES);
    cudaFuncSetAttribute(attn_tc, cudaFuncAttributeMaxDynamicSharedMemorySize,
                         ATTN_SMEM_BYTES);

    // 0) Pre-convert MMA operands to fp16 in global memory
    cvt_h<0><<<(M_TOK * CC / 4 + 255) / 256, 256>>>(x, M_TOK * CC / 4);
    cvt_h<1><<<(QKV_N * CC / 4 + 255) / 256, 256>>>(qkv_w, QKV_N * CC / 4);
    cvt_h<2><<<(CC * ATT_N / 4 + 255) / 256, 256>>>(proj_w, CC * ATT_N / 4);

    // 1) QKV projection + bias -> fp16 q/k/v (q pre-scaled by 1/8)
    dim3 g1(M_TOK / 128, QKV_N / 192);
    gemm_tc<0><<<g1, 512, GEMM_SMEM_BYTES>>>(qkv_b, nullptr, M_TOK, QKV_N, CC);

    // 2) Flash attention -> fp16 g_att [B,N,H*HD]
    dim3 g2(NN / 128, BB * HH);
    attn_tc<<<g2, 128, ATTN_SMEM_BYTES>>>();

    // 3) Output projection + bias (f32 output)
    dim3 g3(M_TOK / 128, CC / 192);
    gemm_tc<1><<<g3, 512, GEMM_SMEM_BYTES>>>(proj_b, out, M_TOK, CC, ATT_N);
}

// round 15
// speedup vs baseline: 2.6636x; 1.0968x over previous
#include <cuda_runtime.h>
#include <cuda_fp16.h>
#include <cstdint>

#define BB 16
#define NN 1024
#define CC 768
#define HH 9
#define HD 64
#define M_TOK (BB * NN)        // 16384
#define QKV_N (3 * HH * HD)    // 1728
#define ATT_N (HH * HD)        // 576

// Scratch (device globals — no allocation allowed). All fp16 operands.
__device__ __half g_q[BB * HH * NN * HD];    // [B,H,N,HD], pre-scaled by 1/8
__device__ __half g_k[BB * HH * NN * HD];
__device__ __half g_v[BB * HH * NN * HD];    // [B,H,N,HD] (row = key, col = d)
__device__ __half g_att[M_TOK * ATT_N];      // [B,N,H*HD]
__device__ __half g_xt[M_TOK * CC];          // fp16 copies of inputs
__device__ __half g_wqkv[QKV_N * CC];
__device__ __half g_wproj[CC * ATT_N];

// ---------------------------------------------------------------------------
// Helpers
// ---------------------------------------------------------------------------
__device__ __forceinline__ uint32_t f2h2(float a, float b) {
    __half2 h = __floats2half2_rn(a, b);
    return *(uint32_t*)&h;
}

__device__ __forceinline__ void cp16(void* smem_dst, const void* gmem_src) {
    uint32_t sa = (uint32_t)__cvta_generic_to_shared(smem_dst);
    asm volatile("cp.async.cg.shared.global [%0], [%1], 16;"
                 :: "r"(sa), "l"(gmem_src));
}
__device__ __forceinline__ void cp_commit() {
    asm volatile("cp.async.commit_group;");
}
template <int N>
__device__ __forceinline__ void cp_wait() {
    asm volatile("cp.async.wait_group %0;" :: "n"(N));
}

// D(16x8,f32) += A(16x16,f16,row) * B(16x8,f16,col)
__device__ __forceinline__ void mma_f16(float* d,
    uint32_t a0, uint32_t a1, uint32_t a2, uint32_t a3,
    uint32_t b0, uint32_t b1)
{
    asm volatile(
        "mma.sync.aligned.m16n8k16.row.col.f32.f16.f16.f32 "
        "{%0,%1,%2,%3}, {%4,%5,%6,%7}, {%8,%9}, {%0,%1,%2,%3};"
        : "+f"(d[0]), "+f"(d[1]), "+f"(d[2]), "+f"(d[3])
        : "r"(a0), "r"(a1), "r"(a2), "r"(a3), "r"(b0), "r"(b1));
}

// ldmatrix x4, non-transposed (A/B/P fragments)
__device__ __forceinline__ void ldsm_x4(
    uint32_t& r0, uint32_t& r1, uint32_t& r2, uint32_t& r3, const void* p)
{
    uint32_t sa = (uint32_t)__cvta_generic_to_shared(p);
    asm volatile("ldmatrix.sync.aligned.m8n8.x4.shared.b16 "
                 "{%0,%1,%2,%3}, [%4];"
                 : "=r"(r0), "=r"(r1), "=r"(r2), "=r"(r3) : "r"(sa));
}

// ldmatrix x4, transposed (V -> PV B-fragments)
__device__ __forceinline__ void ldsm_x4_t(
    uint32_t& r0, uint32_t& r1, uint32_t& r2, uint32_t& r3, const void* p)
{
    uint32_t sa = (uint32_t)__cvta_generic_to_shared(p);
    asm volatile("ldmatrix.sync.aligned.m8n8.x4.trans.shared.b16 "
                 "{%0,%1,%2,%3}, [%4];"
                 : "=r"(r0), "=r"(r1), "=r"(r2), "=r"(r3) : "r"(sa));
}

// ---------------------------------------------------------------------------
// Fused pre-convert of all three fp32 inputs to fp16 (single launch).
// Index space is float4 over [x | qkv_w | proj_w].
// ---------------------------------------------------------------------------
#define NX4 (M_TOK * CC / 4)        // 3145728
#define NW1 (QKV_N * CC / 4)        // 331776
#define NW2 (CC * ATT_N / 4)        // 110592

__global__ __launch_bounds__(256) void cvt_all(
    const float* __restrict__ x, const float* __restrict__ w1,
    const float* __restrict__ w2)
{
    int i = blockIdx.x * 256 + threadIdx.x;
    const float* src;
    __half* dst;
    int j;
    if (i < NX4)                { src = x;  dst = g_xt;    j = i; }
    else if (i < NX4 + NW1)     { src = w1; dst = g_wqkv;  j = i - NX4; }
    else if (i < NX4 + NW1+NW2) { src = w2; dst = g_wproj; j = i - NX4 - NW1; }
    else return;
    float4 v = ((const float4*)src)[j];
    ((uint2*)dst)[j] = make_uint2(f2h2(v.x, v.y), f2h2(v.z, v.w));
}

// ---------------------------------------------------------------------------
// GEMM (fp16 tensor core): C[M,N] = A[M,K] @ B[N,K]^T + bias.
// Block 128x192, BK=32 halves, 512 threads = 16 warps 4(M)x4(N), warp 32x48.
// Fragment loads via ldmatrix.x4: per warp-iter 10 LDSM (was 40 LDS.32).
// smem rows as half2-pairs (u32), stride 20: within each 8x8 matrix the 8
// row-addresses land on distinct bank quads (20r mod 32 all distinct).
// 3-stage cp.async ring, ONE barrier/iter.
// MODE 0: A=g_xt, B=g_wqkv -> scatter fp16 into g_q (x0.125)/g_k/g_v.
// MODE 1: A=g_att, B=g_wproj -> f32 store + bias.
// ---------------------------------------------------------------------------
#define GEMM_SMEM_BYTES (3 * (128 + 192) * 20 * 4)   // 76800

template <int MODE>
__global__ __launch_bounds__(512, 1) void gemm_tc(
    const float* __restrict__ bias, float* __restrict__ C,
    int M, int N, int K)
{
    extern __shared__ uint32_t dsm[];

    const int tid  = threadIdx.x;
    const int lane = tid & 31;
    const int warp = tid >> 5;          // 0..15
    const int wm = warp >> 2;           // 0..3  (M groups of 32)
    const int wn = warp & 3;            // 0..3  (N groups of 48)
    const int g = lane >> 2, t = lane & 3;
    const int bm = blockIdx.x * 128;
    const int bn = blockIdx.y * 192;

    // ldmatrix per-lane offsets (u32 units), stride 20
    const int lr8  = lane & 7;
    const int lm01 = (lane >> 3) & 1;
    const int lm23 = (lane >> 4) & 1;
    const int aoff = (lm01 * 8 + lr8) * 20 + lm23 * 4;  // A/P-style chunk
    const int boff = (lm23 * 8 + lr8) * 20 + lm01 * 4;  // B-style chunk

    const __half* Ah = (MODE == 0) ? g_xt  : g_att;
    const __half* Bh = (MODE == 0) ? g_wqkv : g_wproj;

    float acc[2][6][4];
#pragma unroll
    for (int mt = 0; mt < 2; mt++)
#pragma unroll
        for (int nt = 0; nt < 6; nt++)
#pragma unroll
            for (int i = 0; i < 4; i++) acc[mt][nt][i] = 0.0f;

    // Stage s: A tile (128 rows x 20 u32) then B tile (192 x 20)
    auto issue = [&](int stage, int k0) {
        uint32_t* Asd = dsm + stage * (320 * 20);
        uint32_t* Bsd = Asd + 128 * 20;
        {                                            // A: 512 16B chunks
            int r = tid >> 2, c = tid & 3;
            cp16(&Asd[r * 20 + c * 4], Ah + (size_t)(bm + r) * K + k0 + c * 8);
        }
        for (int idx = tid; idx < 768; idx += 512) { // B: 768 16B chunks
            int r = idx >> 2, c = idx & 3;
            cp16(&Bsd[r * 20 + c * 4], Bh + (size_t)(bn + r) * K + k0 + c * 8);
        }
        cp_commit();
    };

    const int nIter = K / 32;
    issue(0, 0);
    issue(1, 32);

    for (int it = 0; it < nIter; it++) {
        cp_wait<1>();
        __syncthreads();

        if (it + 2 < nIter) issue((it + 2) % 3, (it + 2) * 32);
        else                cp_commit();            // keep wait-ledger counting

        const uint32_t* Asd = dsm + (it % 3) * (320 * 20);
        const uint32_t* Bsd = Asd + 128 * 20;
#pragma unroll
        for (int ks = 0; ks < 2; ks++) {            // two k16 chunks per BK=32
            const int kk = ks * 8;                  // half2-pair index
            uint32_t a[2][4], b[6][2];
#pragma unroll
            for (int mt = 0; mt < 2; mt++) {
                const uint32_t* p = Asd + (wm * 32 + mt * 16) * 20 + kk + aoff;
                ldsm_x4(a[mt][0], a[mt][1], a[mt][2], a[mt][3], p);
            }
#pragma unroll
            for (int ntp = 0; ntp < 3; ntp++) {
                const uint32_t* p = Bsd + (wn * 48 + ntp * 16) * 20 + kk + boff;
                ldsm_x4(b[2 * ntp][0], b[2 * ntp][1],
                        b[2 * ntp + 1][0], b[2 * ntp + 1][1], p);
            }
#pragma unroll
            for (int mt = 0; mt < 2; mt++)
#pragma unroll
                for (int nt = 0; nt < 6; nt++)
                    mma_f16(acc[mt][nt], a[mt][0], a[mt][1], a[mt][2], a[mt][3],
                            b[nt][0], b[nt][1]);
        }
    }

    // Epilogue
    if (MODE == 0) {
#pragma unroll
        for (int mt = 0; mt < 2; mt++) {
#pragma unroll
            for (int half = 0; half < 2; half++) {
                int m = bm + wm * 32 + mt * 16 + g + half * 8;
                int b_ = m >> 10, tok = m & 1023;
#pragma unroll
                for (int nt = 0; nt < 6; nt++) {
                    int col = bn + wn * 48 + nt * 8 + t * 2;
                    int which = col / 576;
                    int rem = col - which * 576;
                    int h = rem >> 6, d = rem & 63;
                    __half* dst = (which == 0) ? g_q : (which == 1) ? g_k : g_v;
                    float v0 = acc[mt][nt][half * 2]     + bias[col];
                    float v1 = acc[mt][nt][half * 2 + 1] + bias[col + 1];
                    if (which == 0) { v0 *= 0.125f; v1 *= 0.125f; }   // exact
                    *(uint32_t*)&dst[(((size_t)(b_ * HH + h) << 10) + tok) * HD + d] =
                        f2h2(v0, v1);
                }
            }
        }
    } else {
#pragma unroll
        for (int mt = 0; mt < 2; mt++) {
#pragma unroll
            for (int half = 0; half < 2; half++) {
                int m = bm + wm * 32 + mt * 16 + g + half * 8;
#pragma unroll
                for (int nt = 0; nt < 6; nt++) {
                    int col = bn + wn * 48 + nt * 8 + t * 2;
                    float2 r = make_float2(acc[mt][nt][half * 2]     + bias[col],
                                           acc[mt][nt][half * 2 + 1] + bias[col + 1]);
                    *(float2*)&C[(size_t)m * N + col] = r;
                }
            }
        }
    }
}

// ---------------------------------------------------------------------------
// Flash attention (fp16 tensor core): block = 128 queries of one (b,h),
// KV tiles 32. 4 warps; each owns 32 query rows. fp32 softmax.
// Fragment loads via ldmatrix (Q/K/P non-trans, V trans).
// smem (u32 units): Qs[128][36] | K 2x[32][36] | V 2x[32][36] | Ps[128][20]
//   = 47104 B -> 4 blocks/SM.
// ---------------------------------------------------------------------------
#define ATTN_SMEM_BYTES ((128*36 + 2*32*36 + 2*32*36 + 128*20) * 4)  // 47104

__global__ __launch_bounds__(128) void attn_tc()
{
    extern __shared__ uint32_t smu[];
    uint32_t* Qs  = smu;                         // [128][36]
    uint32_t* KsB = smu + 128 * 36;              // 2 x [32][36]
    uint32_t* VsB = KsB + 2 * 32 * 36;           // 2 x [32][36]
    uint32_t* Ps  = VsB + 2 * 32 * 36;           // [128][20]

    const int tid  = threadIdx.x;
    const int lane = tid & 31;
    const int warp = tid >> 5;                 // 0..3
    const int g = lane >> 2, t = lane & 3;
    const int bh = blockIdx.y;                 // 0..143
    const int q0 = blockIdx.x * 128;
    const int qr = warp * 32;                  // warp's 32 query rows

    // ldmatrix per-lane offsets
    const int lr8  = lane & 7;
    const int lm01 = (lane >> 3) & 1;
    const int lm23 = (lane >> 4) & 1;
    const int aoff36 = (lm01 * 8 + lr8) * 36 + lm23 * 4;  // Q chunks (A-style)
    const int boff36 = (lm23 * 8 + lr8) * 36 + lm01 * 4;  // K chunks (B-style)
    const int aoff20 = (lm01 * 8 + lr8) * 20 + lm23 * 4;  // P chunks (A-style)

    const __half* Qg = g_q + ((size_t)bh * NN + q0) * HD;
    const __half* Kg = g_k + (size_t)bh * NN * HD;
    const __half* Vg = g_v + (size_t)bh * NN * HD;

    auto issue = [&](int stage, int kt) {
        uint32_t* Kd = KsB + stage * 32 * 36;
        uint32_t* Vd = VsB + stage * 32 * 36;
#pragma unroll
        for (int i = 0; i < 2; i++) {
            int idx = tid + 128 * i;
            int r = idx >> 3, c = idx & 7;
            cp16(&Kd[r * 36 + c * 4], Kg + (size_t)(kt + r) * HD + c * 8);
        }
#pragma unroll
        for (int i = 0; i < 2; i++) {
            int idx = tid + 128 * i;
            int r = idx >> 3, c = idx & 7;
            cp16(&Vd[r * 36 + c * 4], Vg + (size_t)(kt + r) * HD + c * 8);
        }
        cp_commit();
    };

    issue(0, 0);

    // Q tile copy (already fp16, pre-scaled): 1024 uint4
#pragma unroll
    for (int i = 0; i < 8; i++) {
        int idx = tid + 128 * i;
        int r = idx >> 3, c = idx & 7;
        *(uint4*)&Qs[r * 36 + c * 4] = ((const uint4*)Qg)[idx];
    }

    float m_i[2][2], l_i[2][2], o[2][8][4];
#pragma unroll
    for (int mt = 0; mt < 2; mt++) {
        m_i[mt][0] = -1e30f; m_i[mt][1] = -1e30f;
        l_i[mt][0] = 0.0f;   l_i[mt][1] = 0.0f;
#pragma unroll
        for (int nt = 0; nt < 8; nt++)
#pragma unroll
            for (int i = 0; i < 4; i++) o[mt][nt][i] = 0.0f;
    }

    const int nIter = NN / 32;   // 32
    for (int it = 0; it < nIter; it++) {
        const int stage = it & 1;
        if (it + 1 < nIter) {
            issue(stage ^ 1, (it + 1) * 32);
            cp_wait<1>();
        } else {
            cp_wait<0>();
        }
        __syncthreads();

        const uint32_t* Kd = KsB + stage * 32 * 36;
        const uint32_t* Vd = VsB + stage * 32 * 36;

        // S[32x32] = Q(warp rows) @ K^T : HD=64 -> 4 k16 chunks
        float s[2][4][4];
#pragma unroll
        for (int mt = 0; mt < 2; mt++)
#pragma unroll
            for (int nt = 0; nt < 4; nt++)
#pragma unroll
                for (int i = 0; i < 4; i++) s[mt][nt][i] = 0.0f;

#pragma unroll
        for (int ks = 0; ks < 4; ks++) {
            const int kk = ks * 8;               // half2-pair index into d
            uint32_t a[2][4], b[4][2];
#pragma unroll
            for (int mt = 0; mt < 2; mt++) {
                const uint32_t* p = Qs + (qr + mt * 16) * 36 + kk + aoff36;
                ldsm_x4(a[mt][0], a[mt][1], a[mt][2], a[mt][3], p);
            }
#pragma unroll
            for (int ntp = 0; ntp < 2; ntp++) {
                const uint32_t* p = Kd + (ntp * 16) * 36 + kk + boff36;
                ldsm_x4(b[2 * ntp][0], b[2 * ntp][1],
                        b[2 * ntp + 1][0], b[2 * ntp + 1][1], p);
            }
#pragma unroll
            for (int mt = 0; mt < 2; mt++)
#pragma unroll
                for (int nt = 0; nt < 4; nt++)
                    mma_f16(s[mt][nt], a[mt][0], a[mt][1], a[mt][2], a[mt][3],
                            b[nt][0], b[nt][1]);
        }

        // Online softmax per mt: rows r0 = qr+mt*16+g (elems 0,1), r1 = r0+8
#pragma unroll
        for (int mt = 0; mt < 2; mt++) {
            float mt0 = -1e30f, mt1 = -1e30f;
#pragma unroll
            for (int nt = 0; nt < 4; nt++) {
                mt0 = fmaxf(mt0, fmaxf(s[mt][nt][0], s[mt][nt][1]));
                mt1 = fmaxf(mt1, fmaxf(s[mt][nt][2], s[mt][nt][3]));
            }
            mt0 = fmaxf(mt0, __shfl_xor_sync(0xffffffffu, mt0, 1));
            mt0 = fmaxf(mt0, __shfl_xor_sync(0xffffffffu, mt0, 2));
            mt1 = fmaxf(mt1, __shfl_xor_sync(0xffffffffu, mt1, 1));
            mt1 = fmaxf(mt1, __shfl_xor_sync(0xffffffffu, mt1, 2));

            float mn0 = fmaxf(m_i[mt][0], mt0), mn1 = fmaxf(m_i[mt][1], mt1);
            float c0 = __expf(m_i[mt][0] - mn0), c1 = __expf(m_i[mt][1] - mn1);
            m_i[mt][0] = mn0; m_i[mt][1] = mn1;

            float rs0 = 0.0f, rs1 = 0.0f;
            const int r0 = qr + mt * 16 + g;
#pragma unroll
            for (int nt = 0; nt < 4; nt++) {
                float p00 = __expf(s[mt][nt][0] - mn0);
                float p01 = __expf(s[mt][nt][1] - mn0);
                float p10 = __expf(s[mt][nt][2] - mn1);
                float p11 = __expf(s[mt][nt][3] - mn1);
                rs0 += p00 + p01;
                rs1 += p10 + p11;
                int pp = nt * 4 + t;              // half2-pair index (cols nt*8+2t)
                Ps[r0 * 20 + pp]       = f2h2(p00, p01);
                Ps[(r0 + 8) * 20 + pp] = f2h2(p10, p11);
            }
            rs0 += __shfl_xor_sync(0xffffffffu, rs0, 1);
            rs0 += __shfl_xor_sync(0xffffffffu, rs0, 2);
            rs1 += __shfl_xor_sync(0xffffffffu, rs1, 1);
            rs1 += __shfl_xor_sync(0xffffffffu, rs1, 2);
            l_i[mt][0] = l_i[mt][0] * c0 + rs0;
            l_i[mt][1] = l_i[mt][1] * c1 + rs1;
#pragma unroll
            for (int nt = 0; nt < 8; nt++) {
                o[mt][nt][0] *= c0; o[mt][nt][1] *= c0;
                o[mt][nt][2] *= c1; o[mt][nt][3] *= c1;
            }
        }
        __syncwarp();   // Ps rows are warp-private

        // O[32x64] += P[32x32] @ V[32x64] : 2 k16 chunks, V via ldmatrix.trans
#pragma unroll
        for (int ks = 0; ks < 2; ks++) {
            const int kk = ks * 8;
            uint32_t a[2][4];
#pragma unroll
            for (int mt = 0; mt < 2; mt++) {
                const uint32_t* p = Ps + (qr + mt * 16) * 20 + kk + aoff20;
                ldsm_x4(a[mt][0], a[mt][1], a[mt][2], a[mt][3], p);
            }
            const int krow = ks * 16 + (lane & 15);        // key row for ldmatrix
            const int nbase = ((lane >> 4) << 3);          // 0 or 8
#pragma unroll
            for (int ntp = 0; ntp < 4; ntp++) {
                uint32_t b0, b1, b2, b3;
                int ncol = ntp * 16 + nbase;               // d column (halves)
                ldsm_x4_t(b0, b1, b2, b3, &Vd[krow * 36 + (ncol >> 1)]);
#pragma unroll
                for (int mt = 0; mt < 2; mt++) {
                    mma_f16(o[mt][2 * ntp],     a[mt][0], a[mt][1], a[mt][2], a[mt][3], b0, b1);
                    mma_f16(o[mt][2 * ntp + 1], a[mt][0], a[mt][1], a[mt][2], a[mt][3], b2, b3);
                }
            }
        }
        __syncthreads();   // all reads of this K/V stage done before refill
    }

    // Epilogue: normalize, write fp16 g_att [B,N,H*HD]
    const int b_ = bh / HH;
    const int h  = bh - b_ * HH;
#pragma unroll
    for (int mt = 0; mt < 2; mt++) {
        const float inv0 = 1.0f / l_i[mt][0];
        const float inv1 = 1.0f / l_i[mt][1];
        const int tok0 = q0 + qr + mt * 16 + g;
        const int tok1 = tok0 + 8;
        __half* p0 = g_att + (size_t)(b_ * NN + tok0) * ATT_N + h * HD;
        __half* p1 = g_att + (size_t)(b_ * NN + tok1) * ATT_N + h * HD;
#pragma unroll
        for (int nt = 0; nt < 8; nt++) {
            int d = nt * 8 + t * 2;
            *(uint32_t*)(p0 + d) = f2h2(o[mt][nt][0] * inv0, o[mt][nt][1] * inv0);
            *(uint32_t*)(p1 + d) = f2h2(o[mt][nt][2] * inv1, o[mt][nt][3] * inv1);
        }
    }
}

// ---------------------------------------------------------------------------
extern "C" void kernel_launch(void* const* d_in, const int* in_sizes, int n_in,
                              void* d_out, int out_size)
{
    const float* x      = (const float*)d_in[0];
    const float* qkv_w  = (const float*)d_in[1];
    const float* qkv_b  = (const float*)d_in[2];
    const float* proj_w = (const float*)d_in[3];
    const float* proj_b = (const float*)d_in[4];
    float* out = (float*)d_out;

    cudaFuncSetAttribute(gemm_tc<0>, cudaFuncAttributeMaxDynamicSharedMemorySize,
                         GEMM_SMEM_BYTES);
    cudaFuncSetAttribute(gemm_tc<1>, cudaFuncAttributeMaxDynamicSharedMemorySize,
                         GEMM_SMEM_BYTES);
    cudaFuncSetAttribute(attn_tc, cudaFuncAttributeMaxDynamicSharedMemorySize,
                         ATTN_SMEM_BYTES);

    // 0) Pre-convert all MMA operands to fp16 (single fused launch)
    cvt_all<<<(NX4 + NW1 + NW2 + 255) / 256, 256>>>(x, qkv_w, proj_w);

    // 1) QKV projection + bias -> fp16 q/k/v (q pre-scaled by 1/8)
    dim3 g1(M_TOK / 128, QKV_N / 192);
    gemm_tc<0><<<g1, 512, GEMM_SMEM_BYTES>>>(qkv_b, nullptr, M_TOK, QKV_N, CC);

    // 2) Flash attention -> fp16 g_att [B,N,H*HD]
    dim3 g2(NN / 128, BB * HH);
    attn_tc<<<g2, 128, ATTN_SMEM_BYTES>>>();

    // 3) Output projection + bias (f32 output)
    dim3 g3(M_TOK / 128, CC / 192);
    gemm_tc<1><<<g3, 512, GEMM_SMEM_BYTES>>>(proj_b, out, M_TOK, CC, ATT_N);
}